// round 1
// baseline (speedup 1.0000x reference)
#include <cuda_runtime.h>
#include <math.h>

// ---------------- problem constants ----------------
#define BB   32
#define NN_  577
#define DD   384
#define HH   1536
#define LL   12
#define MLD  581          // mem rows allocated (N + 4 history slots)
#define ALD  584          // attn row stride (padded to mult of 8)

// ---------------- scratch (device globals; no allocs allowed) ----------------
__device__ float g_x   [BB * NN_ * DD];
__device__ float g_xn  [BB * NN_ * DD];
__device__ float g_q   [BB * NN_ * DD];
__device__ float g_tmp [BB * NN_ * DD];
__device__ float g_mem [BB * MLD * DD];
__device__ float g_k   [BB * MLD * DD];
__device__ float g_v   [BB * MLD * DD];
__device__ float g_attn[BB * NN_ * ALD];
__device__ float g_h   [BB * NN_ * HH];

// ---------------- build x and mem for one repeat ----------------
// x = [new_cls, input_patches]; mem rows 0..N-1 = x; mem row N+r = new_cls (for
// future repeats); mem rows N..N+r-1 already hold history from earlier repeats.
__global__ void build_x_mem(const float* __restrict__ inp, float* __restrict__ x,
                            float* __restrict__ mem, int r)
{
    int d = threadIdx.x;      // 384
    int n = blockIdx.x;       // 577
    int b = blockIdx.y;       // 32
    long xi = ((long)b * NN_ + n) * DD + d;
    long mi = ((long)b * MLD + n) * DD + d;
    if (n == 0) {
        float val = (r == 0) ? inp[xi] : x[xi];   // new_cls = cls of previous state
        x[xi]   = val;
        mem[mi] = val;
        mem[((long)b * MLD + NN_ + r) * DD + d] = val;  // save into history slot
    } else {
        float val = inp[xi];                      // patches reset from x_prime
        x[xi]   = val;
        mem[mi] = val;
    }
}

// ---------------- layernorm over D=384, one block (128 thr) per row ----------
__global__ void ln_kernel(const float* __restrict__ in, const float* __restrict__ w,
                          const float* __restrict__ bb, float* __restrict__ out,
                          long batchStride)
{
    __shared__ float red[4];
    long off = (long)blockIdx.y * batchStride + (long)blockIdx.x * DD;
    const float* x = in + off;
    float* y = out + off;
    int t = threadIdx.x;   // 128
    float v0 = x[t], v1 = x[t + 128], v2 = x[t + 256];
    float s = v0 + v1 + v2;
    #pragma unroll
    for (int o = 16; o; o >>= 1) s += __shfl_xor_sync(0xffffffffu, s, o);
    if ((t & 31) == 0) red[t >> 5] = s;
    __syncthreads();
    float mu = (red[0] + red[1] + red[2] + red[3]) * (1.f / 384.f);
    float d0 = v0 - mu, d1 = v1 - mu, d2 = v2 - mu;
    float s2 = d0 * d0 + d1 * d1 + d2 * d2;
    #pragma unroll
    for (int o = 16; o; o >>= 1) s2 += __shfl_xor_sync(0xffffffffu, s2, o);
    __syncthreads();
    if ((t & 31) == 0) red[t >> 5] = s2;
    __syncthreads();
    float var = (red[0] + red[1] + red[2] + red[3]) * (1.f / 384.f);
    float rs = rsqrtf(var + 1e-6f);
    y[t]       = d0 * rs * w[t]       + bb[t];
    y[t + 128] = d1 * rs * w[t + 128] + bb[t + 128];
    y[t + 256] = d2 * rs * w[t + 256] + bb[t + 256];
}

// ---------------- softmax over row of length Mc (<=580), scale pre-applied ---
__global__ void softmax_kernel(float* __restrict__ attn, int Mc, float scale)
{
    __shared__ float red[8];
    float* row = attn + ((long)blockIdx.y * NN_ + blockIdx.x) * ALD;
    int t = threadIdx.x;   // 256
    float v[3];
    float mx = -3.0e38f;
    #pragma unroll
    for (int i = 0; i < 3; i++) {
        int c = t + i * 256;
        v[i] = (c < Mc) ? row[c] * scale : -3.0e38f;
        mx = fmaxf(mx, v[i]);
    }
    #pragma unroll
    for (int o = 16; o; o >>= 1) mx = fmaxf(mx, __shfl_xor_sync(0xffffffffu, mx, o));
    if ((t & 31) == 0) red[t >> 5] = mx;
    __syncthreads();
    mx = red[0];
    #pragma unroll
    for (int i = 1; i < 8; i++) mx = fmaxf(mx, red[i]);
    float s = 0.f;
    #pragma unroll
    for (int i = 0; i < 3; i++) { v[i] = expf(v[i] - mx); s += v[i]; }
    #pragma unroll
    for (int o = 16; o; o >>= 1) s += __shfl_xor_sync(0xffffffffu, s, o);
    __syncthreads();
    if ((t & 31) == 0) red[t >> 5] = s;
    __syncthreads();
    s = red[0] + red[1] + red[2] + red[3] + red[4] + red[5] + red[6] + red[7];
    float inv = 1.f / s;
    #pragma unroll
    for (int i = 0; i < 3; i++) {
        int c = t + i * 256;
        if (c < Mc) row[c] = v[i] * inv;
    }
}

// ---------------- tiled SGEMM, 64x64x16, 256 thr, 4x4 per thread -------------
// BT=true : C[m,n] = sum_k A[m,k] * B[n,k]   (A,B both K-major; K % 16 == 0)
// BT=false: C[m,n] = sum_k A[m,k] * B[k,n]   (K may be ragged; fully guarded)
#define TBM 64
#define TBN 64
#define TBK 16
#define EPI_PLAIN 0
#define EPI_BIAS  1
#define EPI_GELU  2
#define EPI_RES   3

template<int EPI, bool BT>
__global__ void __launch_bounds__(256)
gemm_kernel(const float* __restrict__ A, const float* __restrict__ B,
            const float* __restrict__ bias, const float* __restrict__ ls,
            float* __restrict__ C,
            int M, int Nc, int K, int lda, int ldb, int ldc,
            long strA, long strB, long strC)
{
    __shared__ float sA[TBK][TBM + 4];
    __shared__ float sB[TBK][TBN + 4];
    A += (long)blockIdx.z * strA;
    B += (long)blockIdx.z * strB;
    C += (long)blockIdx.z * strC;
    int m0 = blockIdx.y * TBM, n0 = blockIdx.x * TBN;
    int tid = threadIdx.x;
    int tx = tid & 15, ty = tid >> 4;
    int lr = tid >> 2, lq = tid & 3;
    float acc[4][4] = {};

    for (int k0 = 0; k0 < K; k0 += TBK) {
        // ---- A tile (BM x BK) -> sA[k][m] ----
        {
            int gm = m0 + lr;
            int gk = k0 + lq * 4;
            float4 va = make_float4(0.f, 0.f, 0.f, 0.f);
            if (gm < M) {
                const float* p = A + (long)gm * lda + gk;
                if (BT) {
                    va = *(const float4*)p;              // K % 16 == 0 guaranteed
                } else if (gk + 3 < K) {
                    va = *(const float4*)p;
                } else {
                    if (gk + 0 < K) va.x = p[0];
                    if (gk + 1 < K) va.y = p[1];
                    if (gk + 2 < K) va.z = p[2];
                    if (gk + 3 < K) va.w = p[3];
                }
            }
            sA[lq * 4 + 0][lr] = va.x; sA[lq * 4 + 1][lr] = va.y;
            sA[lq * 4 + 2][lr] = va.z; sA[lq * 4 + 3][lr] = va.w;
        }
        // ---- B tile -> sB[k][n] ----
        if (BT) {
            int gn = n0 + lr;
            int gk = k0 + lq * 4;
            float4 vb = make_float4(0.f, 0.f, 0.f, 0.f);
            if (gn < Nc) vb = *(const float4*)(B + (long)gn * ldb + gk);
            sB[lq * 4 + 0][lr] = vb.x; sB[lq * 4 + 1][lr] = vb.y;
            sB[lq * 4 + 2][lr] = vb.z; sB[lq * 4 + 3][lr] = vb.w;
        } else {
            int kk = tid >> 4;
            int nq = tid & 15;
            int gk = k0 + kk;
            int gn = n0 + nq * 4;
            float4 vb = make_float4(0.f, 0.f, 0.f, 0.f);
            if (gk < K) {
                const float* p = B + (long)gk * ldb + gn;
                if (gn + 3 < Nc) {
                    vb = *(const float4*)p;
                } else {
                    if (gn + 0 < Nc) vb.x = p[0];
                    if (gn + 1 < Nc) vb.y = p[1];
                    if (gn + 2 < Nc) vb.z = p[2];
                    if (gn + 3 < Nc) vb.w = p[3];
                }
            }
            *(float4*)&sB[kk][nq * 4] = vb;
        }
        __syncthreads();
        #pragma unroll
        for (int kk = 0; kk < TBK; kk++) {
            float a[4], b2[4];
            *(float4*)a  = *(const float4*)&sA[kk][ty * 4];
            *(float4*)b2 = *(const float4*)&sB[kk][tx * 4];
            #pragma unroll
            for (int i = 0; i < 4; i++)
                #pragma unroll
                for (int j = 0; j < 4; j++)
                    acc[i][j] += a[i] * b2[j];
        }
        __syncthreads();
    }
    // ---- epilogue ----
    #pragma unroll
    for (int i = 0; i < 4; i++) {
        int gm = m0 + ty * 4 + i;
        if (gm >= M) continue;
        #pragma unroll
        for (int j = 0; j < 4; j++) {
            int gn = n0 + tx * 4 + j;
            if (gn >= Nc) continue;
            float v = acc[i][j];
            long ci = (long)gm * ldc + gn;
            if (EPI == EPI_BIAS) {
                v += bias[gn];
            } else if (EPI == EPI_GELU) {
                v += bias[gn];
                v = 0.5f * v * (1.f + erff(v * 0.70710678118654752f));
            } else if (EPI == EPI_RES) {
                v += bias[gn];
                v = v * ls[gn] + C[ci];
            }
            C[ci] = v;
        }
    }
}

// ---------------- host orchestration ----------------
extern "C" void kernel_launch(void* const* d_in, const int* in_sizes, int n_in,
                              void* d_out, int out_size)
{
    const float* x_in  = (const float*)d_in[0];
    const float* n1w   = (const float*)d_in[1];
    const float* n1b   = (const float*)d_in[2];
    const float* qkvw  = (const float*)d_in[3];
    const float* qkvb  = (const float*)d_in[4];
    const float* qnw   = (const float*)d_in[5];
    const float* qnb   = (const float*)d_in[6];
    const float* knw   = (const float*)d_in[7];
    const float* knb   = (const float*)d_in[8];
    const float* anw   = (const float*)d_in[9];
    const float* anb   = (const float*)d_in[10];
    const float* projw = (const float*)d_in[11];
    const float* projb = (const float*)d_in[12];
    const float* ls1   = (const float*)d_in[13];
    const float* n2w   = (const float*)d_in[14];
    const float* n2b   = (const float*)d_in[15];
    const float* fc1w  = (const float*)d_in[16];
    const float* fc1b  = (const float*)d_in[17];
    const float* fc2w  = (const float*)d_in[18];
    const float* fc2b  = (const float*)d_in[19];
    const float* ls2   = (const float*)d_in[20];

    float *gx, *gxn, *gq, *gtmp, *gmem, *gk, *gv, *gattn, *gh;
    cudaGetSymbolAddress((void**)&gx,   g_x);
    cudaGetSymbolAddress((void**)&gxn,  g_xn);
    cudaGetSymbolAddress((void**)&gq,   g_q);
    cudaGetSymbolAddress((void**)&gtmp, g_tmp);
    cudaGetSymbolAddress((void**)&gmem, g_mem);
    cudaGetSymbolAddress((void**)&gk,   g_k);
    cudaGetSymbolAddress((void**)&gv,   g_v);
    cudaGetSymbolAddress((void**)&gattn,g_attn);
    cudaGetSymbolAddress((void**)&gh,   g_h);

    const float scale = 1.0f / sqrtf((float)DD);
    const long  xStride = (long)NN_ * DD;          // per-batch stride of dense x-like bufs
    const long  mStride = (long)MLD * DD;          // per-batch stride of mem-like bufs
    const long  aStride = (long)NN_ * ALD;         // per-batch stride of attn
    const int   Mflat = BB * NN_;                  // 18464
    const dim3  gFlatD(DD / TBN, (Mflat + TBM - 1) / TBM, 1);   // 6 x 289
    const dim3  gFlatH(HH / TBN, (Mflat + TBM - 1) / TBM, 1);   // 24 x 289

    for (int r = 0; r < 4; r++) {
        int curM = NN_ + r;
        build_x_mem<<<dim3(NN_, BB), DD>>>(x_in, gx, gmem, r);

        for (int l = 0; l < LL; l++) {
            const float* Wq = qkvw + (long)l * 3 * DD * DD;
            const float* Wk = Wq + (long)DD * DD;
            const float* Wv = Wk + (long)DD * DD;
            const float* bq = qkvb + (long)l * 3 * DD;
            const float* bk = bq + DD;
            const float* bv = bk + DD;

            // xn = LN(x, norm1)
            ln_kernel<<<dim3(NN_, BB), 128>>>(gx, n1w + l * DD, n1b + l * DD, gxn, xStride);
            // q = xn @ Wq^T + bq ; then LN(q, qn) in place
            gemm_kernel<EPI_BIAS, true><<<gFlatD, 256>>>(gxn, Wq, bq, nullptr, gq,
                Mflat, DD, DD, DD, DD, DD, 0, 0, 0);
            ln_kernel<<<dim3(NN_, BB), 128>>>(gq, qnw + l * DD, qnb + l * DD, gq, xStride);
            // k = mem @ Wk^T + bk ; LN(k, kn)
            dim3 gKV(DD / TBN, (curM + TBM - 1) / TBM, BB);
            gemm_kernel<EPI_BIAS, true><<<gKV, 256>>>(gmem, Wk, bk, nullptr, gk,
                curM, DD, DD, DD, DD, DD, mStride, 0, mStride);
            ln_kernel<<<dim3(curM, BB), 128>>>(gk, knw + l * DD, knb + l * DD, gk, mStride);
            // v = mem @ Wv^T + bv
            gemm_kernel<EPI_BIAS, true><<<gKV, 256>>>(gmem, Wv, bv, nullptr, gv,
                curM, DD, DD, DD, DD, DD, mStride, 0, mStride);
            // logits = q @ k^T   (batched; scale folded into softmax)
            dim3 gLog((curM + TBN - 1) / TBN, (NN_ + TBM - 1) / TBM, BB);
            gemm_kernel<EPI_PLAIN, true><<<gLog, 256>>>(gq, gk, nullptr, nullptr, gattn,
                NN_, curM, DD, DD, DD, ALD, xStride, mStride, aStride);
            softmax_kernel<<<dim3(NN_, BB), 256>>>(gattn, curM, scale);
            // prod = attn @ v   (NN, ragged K)
            dim3 gProd(DD / TBN, (NN_ + TBM - 1) / TBM, BB);
            gemm_kernel<EPI_PLAIN, false><<<gProd, 256>>>(gattn, gv, nullptr, nullptr, gtmp,
                NN_, DD, curM, ALD, DD, DD, aStride, mStride, xStride);
            // LN(prod, an) in place
            ln_kernel<<<dim3(NN_, BB), 128>>>(gtmp, anw + l * DD, anb + l * DD, gtmp, xStride);
            // x += (prod_n @ proj^T + pb) * ls1
            gemm_kernel<EPI_RES, true><<<gFlatD, 256>>>(gtmp, projw + (long)l * DD * DD,
                projb + l * DD, ls1 + l * DD, gx,
                Mflat, DD, DD, DD, DD, DD, 0, 0, 0);
            // xn = LN(x, norm2)
            ln_kernel<<<dim3(NN_, BB), 128>>>(gx, n2w + l * DD, n2b + l * DD, gxn, xStride);
            // h = gelu(xn @ fc1^T + b1)
            gemm_kernel<EPI_GELU, true><<<gFlatH, 256>>>(gxn, fc1w + (long)l * HH * DD,
                fc1b + (long)l * HH, nullptr, gh,
                Mflat, HH, DD, DD, DD, HH, 0, 0, 0);
            // x += (h @ fc2^T + b2) * ls2
            gemm_kernel<EPI_RES, true><<<gFlatD, 256>>>(gh, fc2w + (long)l * DD * HH,
                fc2b + l * DD, ls2 + l * DD, gx,
                Mflat, DD, HH, HH, HH, DD, 0, 0, 0);
        }
    }
    cudaMemcpyAsync(d_out, gx, (size_t)BB * NN_ * DD * sizeof(float),
                    cudaMemcpyDeviceToDevice);
}

// round 2
// speedup vs baseline: 3.5816x; 3.5816x over previous
#include <cuda_runtime.h>
#include <cuda_bf16.h>
#include <math.h>
#include <stdint.h>

// ---------------- problem constants ----------------
#define BB   32
#define NPTS 577
#define DD   384
#define HH   1536
#define LL   12
#define KPAD 640          // padded mem/attention length (multiple of 128)

// ---------------- scratch (device globals; no allocs allowed) ----------------
__device__ float g_x   [BB * NPTS * DD];
__device__ float g_xn  [BB * NPTS * DD];
__device__ float g_q   [BB * NPTS * DD];
__device__ float g_tmp [BB * NPTS * DD];
__device__ float g_mem [BB * KPAD * DD];
__device__ float g_k   [BB * KPAD * DD];
__device__ float g_vt  [BB * DD * KPAD];    // v transposed: [d][mem]
__device__ float g_attn[BB * NPTS * KPAD];
__device__ float g_h   [BB * NPTS * HH];

// ---------------- build x and mem for one repeat ----------------
__global__ void build_x_mem(const float* __restrict__ inp, float* __restrict__ x,
                            float* __restrict__ mem, int r)
{
    int d = threadIdx.x;      // 384
    int n = blockIdx.x;       // 577
    int b = blockIdx.y;       // 32
    long xi = ((long)b * NPTS + n) * DD + d;
    long mi = ((long)b * KPAD + n) * DD + d;
    if (n == 0) {
        float val = (r == 0) ? inp[xi] : x[xi];
        x[xi]   = val;
        mem[mi] = val;
        mem[((long)b * KPAD + NPTS + r) * DD + d] = val;  // history slot
    } else {
        float val = inp[xi];
        x[xi]   = val;
        mem[mi] = val;
    }
}

// ---------------- layernorm over D=384, one block (128 thr) per row ----------
__global__ void ln_kernel(const float* __restrict__ in, const float* __restrict__ w,
                          const float* __restrict__ bb, float* __restrict__ out,
                          long batchStride)
{
    __shared__ float red[4];
    long off = (long)blockIdx.y * batchStride + (long)blockIdx.x * DD;
    const float* x = in + off;
    float* y = out + off;
    int t = threadIdx.x;   // 128
    float v0 = x[t], v1 = x[t + 128], v2 = x[t + 256];
    float s = v0 + v1 + v2;
    #pragma unroll
    for (int o = 16; o; o >>= 1) s += __shfl_xor_sync(0xffffffffu, s, o);
    if ((t & 31) == 0) red[t >> 5] = s;
    __syncthreads();
    float mu = (red[0] + red[1] + red[2] + red[3]) * (1.f / 384.f);
    float d0 = v0 - mu, d1 = v1 - mu, d2 = v2 - mu;
    float s2 = d0 * d0 + d1 * d1 + d2 * d2;
    #pragma unroll
    for (int o = 16; o; o >>= 1) s2 += __shfl_xor_sync(0xffffffffu, s2, o);
    __syncthreads();
    if ((t & 31) == 0) red[t >> 5] = s2;
    __syncthreads();
    float var = (red[0] + red[1] + red[2] + red[3]) * (1.f / 384.f);
    float rs = rsqrtf(var + 1e-6f);
    y[t]       = d0 * rs * w[t]       + bb[t];
    y[t + 128] = d1 * rs * w[t + 128] + bb[t + 128];
    y[t + 256] = d2 * rs * w[t + 256] + bb[t + 256];
}

// ---------------- softmax over row of length KPAD; valid cols < Mc ----------
// Zero-fills [Mc, KPAD) so downstream GEMM can run unguarded K = KPAD.
__global__ void softmax_kernel(float* __restrict__ attn, int Mc, float scale)
{
    __shared__ float red[8];
    float* row = attn + ((long)blockIdx.y * NPTS + blockIdx.x) * KPAD;
    int t = threadIdx.x;   // 256
    float v[3];
    float mx = -3.0e38f;
    #pragma unroll
    for (int i = 0; i < 3; i++) {
        int c = t + i * 256;
        v[i] = (c < Mc) ? row[c] * scale : -3.0e38f;
        mx = fmaxf(mx, v[i]);
    }
    #pragma unroll
    for (int o = 16; o; o >>= 1) mx = fmaxf(mx, __shfl_xor_sync(0xffffffffu, mx, o));
    if ((t & 31) == 0) red[t >> 5] = mx;
    __syncthreads();
    mx = red[0];
    #pragma unroll
    for (int i = 1; i < 8; i++) mx = fmaxf(mx, red[i]);
    float s = 0.f;
    #pragma unroll
    for (int i = 0; i < 3; i++) {
        int c = t + i * 256;
        v[i] = (c < Mc) ? expf(v[i] - mx) : 0.f;
        s += v[i];
    }
    #pragma unroll
    for (int o = 16; o; o >>= 1) s += __shfl_xor_sync(0xffffffffu, s, o);
    __syncthreads();
    if ((t & 31) == 0) red[t >> 5] = s;
    __syncthreads();
    s = red[0] + red[1] + red[2] + red[3] + red[4] + red[5] + red[6] + red[7];
    float inv = 1.f / s;
    #pragma unroll
    for (int i = 0; i < 3; i++) {
        int c = t + i * 256;
        if (c < KPAD) row[c] = v[i] * inv;   // pad cols get 0
    }
}

// ---------------- bf16 tensor-core GEMM ----------------
// C[m,n] = sum_k A[m,k] * B[n,k]   (both K-major, "NT"), fp32 in/out.
// Tiles: BM=128, BN=128, BK=32; 256 threads = 8 warps (2 M x 4 N), warp tile 64x32.
// N and K must be multiples of 128 / 32 respectively; M is guarded.
// STORE_T: write C transposed, element (m,n) -> C[n*ldc + m].
#define BM 128
#define BN 128
#define BKK 32
#define SROWB 80          // smem row pitch in BYTES (32 bf16 = 64B data + 16B pad)
#define EPI_PLAIN 0
#define EPI_BIAS  1
#define EPI_GELU  2
#define EPI_RES   3

__device__ __forceinline__ void ldm4(uint32_t* r, uint32_t addr) {
    asm volatile("ldmatrix.sync.aligned.m8n8.x4.shared.b16 {%0,%1,%2,%3}, [%4];"
        : "=r"(r[0]), "=r"(r[1]), "=r"(r[2]), "=r"(r[3]) : "r"(addr));
}
__device__ __forceinline__ void ldm2(uint32_t* r, uint32_t addr) {
    asm volatile("ldmatrix.sync.aligned.m8n8.x2.shared.b16 {%0,%1}, [%2];"
        : "=r"(r[0]), "=r"(r[1]) : "r"(addr));
}
__device__ __forceinline__ void mma16816(float* c, const uint32_t* a, const uint32_t* b) {
    asm volatile("mma.sync.aligned.m16n8k16.row.col.f32.bf16.bf16.f32 "
        "{%0,%1,%2,%3}, {%4,%5,%6,%7}, {%8,%9}, {%0,%1,%2,%3};"
        : "+f"(c[0]), "+f"(c[1]), "+f"(c[2]), "+f"(c[3])
        : "r"(a[0]), "r"(a[1]), "r"(a[2]), "r"(a[3]), "r"(b[0]), "r"(b[1]));
}

template<int EPI, bool STORE_T>
__global__ void __launch_bounds__(256)
mma_gemm(const float* __restrict__ A, const float* __restrict__ B,
         const float* __restrict__ bias, const float* __restrict__ ls,
         float* __restrict__ C,
         int M, int K, int lda, int ldb, int ldc,
         long strA, long strB, long strC)
{
    __shared__ __align__(16) char sA[BM * SROWB];
    __shared__ __align__(16) char sB[BN * SROWB];
    A += (long)blockIdx.z * strA;
    B += (long)blockIdx.z * strB;
    C += (long)blockIdx.z * strC;
    int m0 = blockIdx.y * BM, n0 = blockIdx.x * BN;
    int t = threadIdx.x;
    int warp = t >> 5, lane = t & 31;
    int wm = warp & 1;          // 0..1
    int wn = warp >> 1;         // 0..3

    float acc[4][4][4];
    #pragma unroll
    for (int i = 0; i < 4; i++)
        #pragma unroll
        for (int j = 0; j < 4; j++)
            #pragma unroll
            for (int q = 0; q < 4; q++) acc[i][j][q] = 0.f;

    uint32_t sAb = (uint32_t)__cvta_generic_to_shared(sA);
    uint32_t sBb = (uint32_t)__cvta_generic_to_shared(sB);

    // fragment-load base addresses
    uint32_t aAddr = sAb + (uint32_t)((wm * 64 + (lane & 15)) * SROWB + (lane >> 4) * 16);
    uint32_t bAddr = sBb + (uint32_t)((wn * 32 + (lane & 7)) * SROWB + ((lane >> 3) & 1) * 16);

    int ldRow = t >> 3;          // 0..31 (base row for staging)
    int ldK   = (t & 7) * 4;     // k offset (float4)

    for (int k0 = 0; k0 < K; k0 += BKK) {
        // ---- stage A (M-guarded) ----
        #pragma unroll
        for (int i = 0; i < 4; i++) {
            int r = ldRow + i * 32;
            float4 v = make_float4(0.f, 0.f, 0.f, 0.f);
            int gm = m0 + r;
            if (gm < M) v = *(const float4*)(A + (long)gm * lda + (k0 + ldK));
            __nv_bfloat162 p0 = __floats2bfloat162_rn(v.x, v.y);
            __nv_bfloat162 p1 = __floats2bfloat162_rn(v.z, v.w);
            uint2 u = make_uint2(*(uint32_t*)&p0, *(uint32_t*)&p1);
            *(uint2*)(sA + r * SROWB + ldK * 2) = u;
        }
        // ---- stage B (unguarded: N multiple of 128, rows exist) ----
        #pragma unroll
        for (int i = 0; i < 4; i++) {
            int r = ldRow + i * 32;
            float4 v = *(const float4*)(B + (long)(n0 + r) * ldb + (k0 + ldK));
            __nv_bfloat162 p0 = __floats2bfloat162_rn(v.x, v.y);
            __nv_bfloat162 p1 = __floats2bfloat162_rn(v.z, v.w);
            uint2 u = make_uint2(*(uint32_t*)&p0, *(uint32_t*)&p1);
            *(uint2*)(sB + r * SROWB + ldK * 2) = u;
        }
        __syncthreads();
        #pragma unroll
        for (int kk = 0; kk < 2; kk++) {
            uint32_t af[4][4], bf_[4][2];
            #pragma unroll
            for (int mt = 0; mt < 4; mt++)
                ldm4(af[mt], aAddr + (uint32_t)(mt * 16 * SROWB + kk * 32));
            #pragma unroll
            for (int nt = 0; nt < 4; nt++)
                ldm2(bf_[nt], bAddr + (uint32_t)(nt * 8 * SROWB + kk * 32));
            #pragma unroll
            for (int mt = 0; mt < 4; mt++)
                #pragma unroll
                for (int nt = 0; nt < 4; nt++)
                    mma16816(acc[mt][nt], af[mt], bf_[nt]);
        }
        __syncthreads();
    }

    // ---- epilogue ----
    int g = lane >> 2, tg = lane & 3;
    #pragma unroll
    for (int mt = 0; mt < 4; mt++) {
        #pragma unroll
        for (int nt = 0; nt < 4; nt++) {
            int gm = m0 + wm * 64 + mt * 16 + g;
            int gn = n0 + wn * 32 + nt * 8 + tg * 2;
            float* cc = acc[mt][nt];
            float b0 = 0.f, b1 = 0.f, l0 = 0.f, l1 = 0.f;
            if (EPI != EPI_PLAIN) { float2 bv = *(const float2*)&bias[gn]; b0 = bv.x; b1 = bv.y; }
            if (EPI == EPI_RES)   { float2 lv = *(const float2*)&ls[gn];   l0 = lv.x; l1 = lv.y; }
            #pragma unroll
            for (int h = 0; h < 2; h++) {
                int gmh = gm + h * 8;
                if (gmh >= M) continue;
                float v0 = cc[h * 2 + 0], v1 = cc[h * 2 + 1];
                if (EPI == EPI_BIAS) { v0 += b0; v1 += b1; }
                else if (EPI == EPI_GELU) {
                    v0 += b0; v1 += b1;
                    v0 = 0.5f * v0 * (1.f + erff(v0 * 0.70710678118654752f));
                    v1 = 0.5f * v1 * (1.f + erff(v1 * 0.70710678118654752f));
                }
                if (STORE_T) {
                    // transposed store: (m,n) -> C[n*ldc + m]
                    C[(long)gn * ldc + gmh]       = v0;
                    C[(long)(gn + 1) * ldc + gmh] = v1;
                } else {
                    long ci = (long)gmh * ldc + gn;
                    if (EPI == EPI_RES) {
                        float2 old = *(float2*)&C[ci];
                        v0 = (v0 + b0) * l0 + old.x;
                        v1 = (v1 + b1) * l1 + old.y;
                    }
                    *(float2*)&C[ci] = make_float2(v0, v1);
                }
            }
        }
    }
}

// ---------------- host orchestration ----------------
extern "C" void kernel_launch(void* const* d_in, const int* in_sizes, int n_in,
                              void* d_out, int out_size)
{
    const float* x_in  = (const float*)d_in[0];
    const float* n1w   = (const float*)d_in[1];
    const float* n1b   = (const float*)d_in[2];
    const float* qkvw  = (const float*)d_in[3];
    const float* qkvb  = (const float*)d_in[4];
    const float* qnw   = (const float*)d_in[5];
    const float* qnb   = (const float*)d_in[6];
    const float* knw   = (const float*)d_in[7];
    const float* knb   = (const float*)d_in[8];
    const float* anw   = (const float*)d_in[9];
    const float* anb   = (const float*)d_in[10];
    const float* projw = (const float*)d_in[11];
    const float* projb = (const float*)d_in[12];
    const float* ls1   = (const float*)d_in[13];
    const float* n2w   = (const float*)d_in[14];
    const float* n2b   = (const float*)d_in[15];
    const float* fc1w  = (const float*)d_in[16];
    const float* fc1b  = (const float*)d_in[17];
    const float* fc2w  = (const float*)d_in[18];
    const float* fc2b  = (const float*)d_in[19];
    const float* ls2   = (const float*)d_in[20];

    float *gx, *gxn, *gq, *gtmp, *gmem, *gk, *gvt, *gattn, *gh;
    cudaGetSymbolAddress((void**)&gx,   g_x);
    cudaGetSymbolAddress((void**)&gxn,  g_xn);
    cudaGetSymbolAddress((void**)&gq,   g_q);
    cudaGetSymbolAddress((void**)&gtmp, g_tmp);
    cudaGetSymbolAddress((void**)&gmem, g_mem);
    cudaGetSymbolAddress((void**)&gk,   g_k);
    cudaGetSymbolAddress((void**)&gvt,  g_vt);
    cudaGetSymbolAddress((void**)&gattn,g_attn);
    cudaGetSymbolAddress((void**)&gh,   g_h);

    const float scale = 1.0f / sqrtf((float)DD);
    const long xStride = (long)NPTS * DD;
    const long mStride = (long)KPAD * DD;     // mem/k per-batch stride
    const long vtStride = (long)DD * KPAD;    // vT per-batch stride
    const long aStride = (long)NPTS * KPAD;
    const int  Mflat = BB * NPTS;             // 18464
    const dim3 gFlatD(DD / BN, (Mflat + BM - 1) / BM, 1);    // 3 x 145
    const dim3 gFlatH(HH / BN, (Mflat + BM - 1) / BM, 1);    // 12 x 145

    for (int r = 0; r < 4; r++) {
        int curM = NPTS + r;
        build_x_mem<<<dim3(NPTS, BB), DD>>>(x_in, gx, gmem, r);

        for (int l = 0; l < LL; l++) {
            const float* Wq = qkvw + (long)l * 3 * DD * DD;
            const float* Wk = Wq + (long)DD * DD;
            const float* Wv = Wk + (long)DD * DD;
            const float* bq = qkvb + (long)l * 3 * DD;
            const float* bk = bq + DD;
            const float* bv = bk + DD;

            // xn = LN(x, norm1)
            ln_kernel<<<dim3(NPTS, BB), 128>>>(gx, n1w + l * DD, n1b + l * DD, gxn, xStride);
            // q = xn @ Wq^T + bq ; LN(q, qn)
            mma_gemm<EPI_BIAS, false><<<gFlatD, 256>>>(gxn, Wq, bq, nullptr, gq,
                Mflat, DD, DD, DD, DD, 0, 0, 0);
            ln_kernel<<<dim3(NPTS, BB), 128>>>(gq, qnw + l * DD, qnb + l * DD, gq, xStride);
            // k = mem @ Wk^T + bk ; LN(k, kn)   (batched, M = curM)
            dim3 gKV(DD / BN, (curM + BM - 1) / BM, BB);
            mma_gemm<EPI_BIAS, false><<<gKV, 256>>>(gmem, Wk, bk, nullptr, gk,
                curM, DD, DD, DD, DD, mStride, 0, mStride);
            ln_kernel<<<dim3(curM, BB), 128>>>(gk, knw + l * DD, knb + l * DD, gk, mStride);
            // vT[d][mem] = (mem @ Wv^T + bv)^T   (transposed store)
            mma_gemm<EPI_BIAS, true><<<gKV, 256>>>(gmem, Wv, bv, nullptr, gvt,
                curM, DD, DD, DD, KPAD, mStride, 0, vtStride);
            // logits = q @ k^T  (N = KPAD unguarded; pad cols zeroed by softmax)
            dim3 gLog(KPAD / BN, (NPTS + BM - 1) / BM, BB);
            mma_gemm<EPI_PLAIN, false><<<gLog, 256>>>(gq, gk, nullptr, nullptr, gattn,
                NPTS, DD, DD, DD, KPAD, xStride, mStride, aStride);
            softmax_kernel<<<dim3(NPTS, BB), 256>>>(gattn, curM, scale);
            // prod = attn @ v = attn @ vT^T   (NT, K = KPAD)
            dim3 gProd(DD / BN, (NPTS + BM - 1) / BM, BB);
            mma_gemm<EPI_PLAIN, false><<<gProd, 256>>>(gattn, gvt, nullptr, nullptr, gtmp,
                NPTS, KPAD, KPAD, KPAD, DD, aStride, vtStride, xStride);
            // LN(prod, an)
            ln_kernel<<<dim3(NPTS, BB), 128>>>(gtmp, anw + l * DD, anb + l * DD, gtmp, xStride);
            // x += (prod_n @ proj^T + pb) * ls1
            mma_gemm<EPI_RES, false><<<gFlatD, 256>>>(gtmp, projw + (long)l * DD * DD,
                projb + l * DD, ls1 + l * DD, gx,
                Mflat, DD, DD, DD, DD, 0, 0, 0);
            // xn = LN(x, norm2)
            ln_kernel<<<dim3(NPTS, BB), 128>>>(gx, n2w + l * DD, n2b + l * DD, gxn, xStride);
            // h = gelu(xn @ fc1^T + b1)
            mma_gemm<EPI_GELU, false><<<gFlatH, 256>>>(gxn, fc1w + (long)l * HH * DD,
                fc1b + (long)l * HH, nullptr, gh,
                Mflat, DD, DD, DD, HH, 0, 0, 0);
            // x += (h @ fc2^T + b2) * ls2
            mma_gemm<EPI_RES, false><<<gFlatD, 256>>>(gh, fc2w + (long)l * DD * HH,
                fc2b + l * DD, ls2 + l * DD, gx,
                Mflat, HH, HH, HH, DD, 0, 0, 0);
        }
    }
    cudaMemcpyAsync(d_out, gx, (size_t)BB * NPTS * DD * sizeof(float),
                    cudaMemcpyDeviceToDevice);
}

// round 3
// speedup vs baseline: 3.6318x; 1.0140x over previous
#include <cuda_runtime.h>
#include <cuda_bf16.h>
#include <math.h>
#include <stdint.h>

// ---------------- problem constants ----------------
#define BB   32
#define NPTS 577
#define DD   384
#define HH   1536
#define LL   12
#define KPAD 640          // padded mem/attention length (multiple of 128)

// ---------------- scratch (device globals; no allocs allowed) ----------------
__device__ float g_x   [BB * NPTS * DD];
__device__ float g_xn  [BB * NPTS * DD];
__device__ float g_q   [BB * NPTS * DD];
__device__ float g_tmp [BB * NPTS * DD];
__device__ float g_mem [BB * KPAD * DD];
__device__ float g_k   [BB * KPAD * DD];
__device__ float g_vt  [BB * DD * KPAD];    // v transposed: [d][mem]
__device__ float g_attn[BB * NPTS * KPAD];
__device__ float g_h   [BB * NPTS * HH];

// ---------------- build x and mem for one repeat ----------------
__global__ void build_x_mem(const float* __restrict__ inp, float* __restrict__ x,
                            float* __restrict__ mem, int r)
{
    int d = threadIdx.x;      // 384
    int n = blockIdx.x;       // 577
    int b = blockIdx.y;       // 32
    long xi = ((long)b * NPTS + n) * DD + d;
    long mi = ((long)b * KPAD + n) * DD + d;
    if (n == 0) {
        float val = (r == 0) ? inp[xi] : x[xi];
        x[xi]   = val;
        mem[mi] = val;
        mem[((long)b * KPAD + NPTS + r) * DD + d] = val;  // history slot
    } else {
        float val = inp[xi];
        x[xi]   = val;
        mem[mi] = val;
    }
}

// ---------------- layernorm over D=384, one block (128 thr) per row ----------
__global__ void ln_kernel(const float* __restrict__ in, const float* __restrict__ w,
                          const float* __restrict__ bb, float* __restrict__ out,
                          long batchStride)
{
    __shared__ float red[4];
    long off = (long)blockIdx.y * batchStride + (long)blockIdx.x * DD;
    const float* x = in + off;
    float* y = out + off;
    int t = threadIdx.x;   // 128
    float v0 = x[t], v1 = x[t + 128], v2 = x[t + 256];
    float s = v0 + v1 + v2;
    #pragma unroll
    for (int o = 16; o; o >>= 1) s += __shfl_xor_sync(0xffffffffu, s, o);
    if ((t & 31) == 0) red[t >> 5] = s;
    __syncthreads();
    float mu = (red[0] + red[1] + red[2] + red[3]) * (1.f / 384.f);
    float d0 = v0 - mu, d1 = v1 - mu, d2 = v2 - mu;
    float s2 = d0 * d0 + d1 * d1 + d2 * d2;
    #pragma unroll
    for (int o = 16; o; o >>= 1) s2 += __shfl_xor_sync(0xffffffffu, s2, o);
    __syncthreads();
    if ((t & 31) == 0) red[t >> 5] = s2;
    __syncthreads();
    float var = (red[0] + red[1] + red[2] + red[3]) * (1.f / 384.f);
    float rs = rsqrtf(var + 1e-6f);
    y[t]       = d0 * rs * w[t]       + bb[t];
    y[t + 128] = d1 * rs * w[t + 128] + bb[t + 128];
    y[t + 256] = d2 * rs * w[t + 256] + bb[t + 256];
}

// ---------------- softmax over row of length KPAD; valid cols < Mc ----------
// Zero-fills [Mc, KPAD) so downstream GEMM can run unguarded K = KPAD.
__global__ void softmax_kernel(float* __restrict__ attn, int Mc, float scale)
{
    __shared__ float red[8];
    float* row = attn + ((long)blockIdx.y * NPTS + blockIdx.x) * KPAD;
    int t = threadIdx.x;   // 256
    float v[3];
    float mx = -3.0e38f;
    #pragma unroll
    for (int i = 0; i < 3; i++) {
        int c = t + i * 256;
        v[i] = (c < Mc) ? row[c] * scale : -3.0e38f;
        mx = fmaxf(mx, v[i]);
    }
    #pragma unroll
    for (int o = 16; o; o >>= 1) mx = fmaxf(mx, __shfl_xor_sync(0xffffffffu, mx, o));
    if ((t & 31) == 0) red[t >> 5] = mx;
    __syncthreads();
    mx = red[0];
    #pragma unroll
    for (int i = 1; i < 8; i++) mx = fmaxf(mx, red[i]);
    float s = 0.f;
    #pragma unroll
    for (int i = 0; i < 3; i++) {
        int c = t + i * 256;
        v[i] = (c < Mc) ? expf(v[i] - mx) : 0.f;
        s += v[i];
    }
    #pragma unroll
    for (int o = 16; o; o >>= 1) s += __shfl_xor_sync(0xffffffffu, s, o);
    __syncthreads();
    if ((t & 31) == 0) red[t >> 5] = s;
    __syncthreads();
    s = red[0] + red[1] + red[2] + red[3] + red[4] + red[5] + red[6] + red[7];
    float inv = 1.f / s;
    #pragma unroll
    for (int i = 0; i < 3; i++) {
        int c = t + i * 256;
        if (c < KPAD) row[c] = v[i] * inv;   // pad cols get 0
    }
}

// ---------------- bf16 tensor-core GEMM ----------------
// C[m,n] = sum_k A[m,k] * B[n,k]   (both K-major, "NT"), fp32 in/out.
// Tiles: BM=128, BN=128, BK=32; 256 threads = 8 warps (2 M x 4 N), warp tile 64x32.
// N and K must be multiples of 128 / 32 respectively; M is guarded.
// STORE_T: write C transposed, element (m,n) -> C[n*ldc + m].
#define BM 128
#define BN 128
#define BKK 32
#define SROWB 80          // smem row pitch in BYTES (32 bf16 = 64B data + 16B pad)
#define EPI_PLAIN 0
#define EPI_BIAS  1
#define EPI_GELU  2
#define EPI_RES   3

__device__ __forceinline__ void ldm4(uint32_t* r, uint32_t addr) {
    asm volatile("ldmatrix.sync.aligned.m8n8.x4.shared.b16 {%0,%1,%2,%3}, [%4];"
        : "=r"(r[0]), "=r"(r[1]), "=r"(r[2]), "=r"(r[3]) : "r"(addr));
}
__device__ __forceinline__ void ldm2(uint32_t* r, uint32_t addr) {
    asm volatile("ldmatrix.sync.aligned.m8n8.x2.shared.b16 {%0,%1}, [%2];"
        : "=r"(r[0]), "=r"(r[1]) : "r"(addr));
}
__device__ __forceinline__ void mma16816(float* c, const uint32_t* a, const uint32_t* b) {
    asm volatile("mma.sync.aligned.m16n8k16.row.col.f32.bf16.bf16.f32 "
        "{%0,%1,%2,%3}, {%4,%5,%6,%7}, {%8,%9}, {%0,%1,%2,%3};"
        : "+f"(c[0]), "+f"(c[1]), "+f"(c[2]), "+f"(c[3])
        : "r"(a[0]), "r"(a[1]), "r"(a[2]), "r"(a[3]), "r"(b[0]), "r"(b[1]));
}

template<int EPI, bool STORE_T>
__global__ void __launch_bounds__(256)
mma_gemm(const float* __restrict__ A, const float* __restrict__ B,
         const float* __restrict__ bias, const float* __restrict__ ls,
         float* __restrict__ C,
         int M, int K, int lda, int ldb, int ldc,
         long strA, long strB, long strC)
{
    __shared__ __align__(16) char sA[BM * SROWB];
    __shared__ __align__(16) char sB[BN * SROWB];
    A += (long)blockIdx.z * strA;
    B += (long)blockIdx.z * strB;
    C += (long)blockIdx.z * strC;
    int m0 = blockIdx.y * BM, n0 = blockIdx.x * BN;
    int t = threadIdx.x;
    int warp = t >> 5, lane = t & 31;
    int wm = warp & 1;          // 0..1
    int wn = warp >> 1;         // 0..3

    float acc[4][4][4];
    #pragma unroll
    for (int i = 0; i < 4; i++)
        #pragma unroll
        for (int j = 0; j < 4; j++)
            #pragma unroll
            for (int q = 0; q < 4; q++) acc[i][j][q] = 0.f;

    uint32_t sAb = (uint32_t)__cvta_generic_to_shared(sA);
    uint32_t sBb = (uint32_t)__cvta_generic_to_shared(sB);

    // fragment-load base addresses
    uint32_t aAddr = sAb + (uint32_t)((wm * 64 + (lane & 15)) * SROWB + (lane >> 4) * 16);
    uint32_t bAddr = sBb + (uint32_t)((wn * 32 + (lane & 7)) * SROWB + ((lane >> 3) & 1) * 16);

    int ldRow = t >> 3;          // 0..31 (base row for staging)
    int ldK   = (t & 7) * 4;     // k offset (float4)

    for (int k0 = 0; k0 < K; k0 += BKK) {
        // ---- stage A (M-guarded) ----
        #pragma unroll
        for (int i = 0; i < 4; i++) {
            int r = ldRow + i * 32;
            float4 v = make_float4(0.f, 0.f, 0.f, 0.f);
            int gm = m0 + r;
            if (gm < M) v = *(const float4*)(A + (long)gm * lda + (k0 + ldK));
            __nv_bfloat162 p0 = __floats2bfloat162_rn(v.x, v.y);
            __nv_bfloat162 p1 = __floats2bfloat162_rn(v.z, v.w);
            uint2 u = make_uint2(*(uint32_t*)&p0, *(uint32_t*)&p1);
            *(uint2*)(sA + r * SROWB + ldK * 2) = u;
        }
        // ---- stage B (unguarded: N multiple of 128, rows exist) ----
        #pragma unroll
        for (int i = 0; i < 4; i++) {
            int r = ldRow + i * 32;
            float4 v = *(const float4*)(B + (long)(n0 + r) * ldb + (k0 + ldK));
            __nv_bfloat162 p0 = __floats2bfloat162_rn(v.x, v.y);
            __nv_bfloat162 p1 = __floats2bfloat162_rn(v.z, v.w);
            uint2 u = make_uint2(*(uint32_t*)&p0, *(uint32_t*)&p1);
            *(uint2*)(sB + r * SROWB + ldK * 2) = u;
        }
        __syncthreads();
        #pragma unroll
        for (int kk = 0; kk < 2; kk++) {
            uint32_t af[4][4], bf_[4][2];
            #pragma unroll
            for (int mt = 0; mt < 4; mt++)
                ldm4(af[mt], aAddr + (uint32_t)(mt * 16 * SROWB + kk * 32));
            #pragma unroll
            for (int nt = 0; nt < 4; nt++)
                ldm2(bf_[nt], bAddr + (uint32_t)(nt * 8 * SROWB + kk * 32));
            #pragma unroll
            for (int mt = 0; mt < 4; mt++)
                #pragma unroll
                for (int nt = 0; nt < 4; nt++)
                    mma16816(acc[mt][nt], af[mt], bf_[nt]);
        }
        __syncthreads();
    }

    // ---- epilogue ----
    int g = lane >> 2, tg = lane & 3;
    #pragma unroll
    for (int mt = 0; mt < 4; mt++) {
        #pragma unroll
        for (int nt = 0; nt < 4; nt++) {
            int gm = m0 + wm * 64 + mt * 16 + g;
            int gn = n0 + wn * 32 + nt * 8 + tg * 2;
            float* cc = acc[mt][nt];
            float b0 = 0.f, b1 = 0.f, l0 = 0.f, l1 = 0.f;
            if (EPI != EPI_PLAIN) { float2 bv = *(const float2*)&bias[gn]; b0 = bv.x; b1 = bv.y; }
            if (EPI == EPI_RES)   { float2 lv = *(const float2*)&ls[gn];   l0 = lv.x; l1 = lv.y; }
            #pragma unroll
            for (int h = 0; h < 2; h++) {
                int gmh = gm + h * 8;
                if (gmh >= M) continue;
                float v0 = cc[h * 2 + 0], v1 = cc[h * 2 + 1];
                if (EPI == EPI_BIAS) { v0 += b0; v1 += b1; }
                else if (EPI == EPI_GELU) {
                    v0 += b0; v1 += b1;
                    v0 = 0.5f * v0 * (1.f + erff(v0 * 0.70710678118654752f));
                    v1 = 0.5f * v1 * (1.f + erff(v1 * 0.70710678118654752f));
                }
                if (STORE_T) {
                    // transposed store: (m,n) -> C[n*ldc + m]
                    C[(long)gn * ldc + gmh]       = v0;
                    C[(long)(gn + 1) * ldc + gmh] = v1;
                } else {
                    long ci = (long)gmh * ldc + gn;
                    if (EPI == EPI_RES) {
                        float2 old = *(float2*)&C[ci];
                        v0 = (v0 + b0) * l0 + old.x;
                        v1 = (v1 + b1) * l1 + old.y;
                    }
                    *(float2*)&C[ci] = make_float2(v0, v1);
                }
            }
        }
    }
}

// ---------------- host orchestration ----------------
extern "C" void kernel_launch(void* const* d_in, const int* in_sizes, int n_in,
                              void* d_out, int out_size)
{
    const float* x_in  = (const float*)d_in[0];
    const float* n1w   = (const float*)d_in[1];
    const float* n1b   = (const float*)d_in[2];
    const float* qkvw  = (const float*)d_in[3];
    const float* qkvb  = (const float*)d_in[4];
    const float* qnw   = (const float*)d_in[5];
    const float* qnb   = (const float*)d_in[6];
    const float* knw   = (const float*)d_in[7];
    const float* knb   = (const float*)d_in[8];
    const float* anw   = (const float*)d_in[9];
    const float* anb   = (const float*)d_in[10];
    const float* projw = (const float*)d_in[11];
    const float* projb = (const float*)d_in[12];
    const float* ls1   = (const float*)d_in[13];
    const float* n2w   = (const float*)d_in[14];
    const float* n2b   = (const float*)d_in[15];
    const float* fc1w  = (const float*)d_in[16];
    const float* fc1b  = (const float*)d_in[17];
    const float* fc2w  = (const float*)d_in[18];
    const float* fc2b  = (const float*)d_in[19];
    const float* ls2   = (const float*)d_in[20];

    float *gx, *gxn, *gq, *gtmp, *gmem, *gk, *gvt, *gattn, *gh;
    cudaGetSymbolAddress((void**)&gx,   g_x);
    cudaGetSymbolAddress((void**)&gxn,  g_xn);
    cudaGetSymbolAddress((void**)&gq,   g_q);
    cudaGetSymbolAddress((void**)&gtmp, g_tmp);
    cudaGetSymbolAddress((void**)&gmem, g_mem);
    cudaGetSymbolAddress((void**)&gk,   g_k);
    cudaGetSymbolAddress((void**)&gvt,  g_vt);
    cudaGetSymbolAddress((void**)&gattn,g_attn);
    cudaGetSymbolAddress((void**)&gh,   g_h);

    const float scale = 1.0f / sqrtf((float)DD);
    const long xStride = (long)NPTS * DD;
    const long mStride = (long)KPAD * DD;     // mem/k per-batch stride
    const long vtStride = (long)DD * KPAD;    // vT per-batch stride
    const long aStride = (long)NPTS * KPAD;
    const int  Mflat = BB * NPTS;             // 18464
    const dim3 gFlatD(DD / BN, (Mflat + BM - 1) / BM, 1);    // 3 x 145
    const dim3 gFlatH(HH / BN, (Mflat + BM - 1) / BM, 1);    // 12 x 145

    for (int r = 0; r < 4; r++) {
        int curM = NPTS + r;
        build_x_mem<<<dim3(NPTS, BB), DD>>>(x_in, gx, gmem, r);

        for (int l = 0; l < LL; l++) {
            const float* Wq = qkvw + (long)l * 3 * DD * DD;
            const float* Wk = Wq + (long)DD * DD;
            const float* Wv = Wk + (long)DD * DD;
            const float* bq = qkvb + (long)l * 3 * DD;
            const float* bk = bq + DD;
            const float* bv = bk + DD;

            // xn = LN(x, norm1)
            ln_kernel<<<dim3(NPTS, BB), 128>>>(gx, n1w + l * DD, n1b + l * DD, gxn, xStride);
            // q = xn @ Wq^T + bq ; LN(q, qn)
            mma_gemm<EPI_BIAS, false><<<gFlatD, 256>>>(gxn, Wq, bq, nullptr, gq,
                Mflat, DD, DD, DD, DD, 0, 0, 0);
            ln_kernel<<<dim3(NPTS, BB), 128>>>(gq, qnw + l * DD, qnb + l * DD, gq, xStride);
            // k = mem @ Wk^T + bk ; LN(k, kn)   (batched, M = curM)
            dim3 gKV(DD / BN, (curM + BM - 1) / BM, BB);
            mma_gemm<EPI_BIAS, false><<<gKV, 256>>>(gmem, Wk, bk, nullptr, gk,
                curM, DD, DD, DD, DD, mStride, 0, mStride);
            ln_kernel<<<dim3(curM, BB), 128>>>(gk, knw + l * DD, knb + l * DD, gk, mStride);
            // vT[d][mem] = (mem @ Wv^T + bv)^T   (transposed store)
            mma_gemm<EPI_BIAS, true><<<gKV, 256>>>(gmem, Wv, bv, nullptr, gvt,
                curM, DD, DD, DD, KPAD, mStride, 0, vtStride);
            // logits = q @ k^T  (N = KPAD unguarded; pad cols zeroed by softmax)
            dim3 gLog(KPAD / BN, (NPTS + BM - 1) / BM, BB);
            mma_gemm<EPI_PLAIN, false><<<gLog, 256>>>(gq, gk, nullptr, nullptr, gattn,
                NPTS, DD, DD, DD, KPAD, xStride, mStride, aStride);
            softmax_kernel<<<dim3(NPTS, BB), 256>>>(gattn, curM, scale);
            // prod = attn @ v = attn @ vT^T   (NT, K = KPAD)
            dim3 gProd(DD / BN, (NPTS + BM - 1) / BM, BB);
            mma_gemm<EPI_PLAIN, false><<<gProd, 256>>>(gattn, gvt, nullptr, nullptr, gtmp,
                NPTS, KPAD, KPAD, KPAD, DD, aStride, vtStride, xStride);
            // LN(prod, an)
            ln_kernel<<<dim3(NPTS, BB), 128>>>(gtmp, anw + l * DD, anb + l * DD, gtmp, xStride);
            // x += (prod_n @ proj^T + pb) * ls1
            mma_gemm<EPI_RES, false><<<gFlatD, 256>>>(gtmp, projw + (long)l * DD * DD,
                projb + l * DD, ls1 + l * DD, gx,
                Mflat, DD, DD, DD, DD, 0, 0, 0);
            // xn = LN(x, norm2)
            ln_kernel<<<dim3(NPTS, BB), 128>>>(gx, n2w + l * DD, n2b + l * DD, gxn, xStride);
            // h = gelu(xn @ fc1^T + b1)
            mma_gemm<EPI_GELU, false><<<gFlatH, 256>>>(gxn, fc1w + (long)l * HH * DD,
                fc1b + (long)l * HH, nullptr, gh,
                Mflat, DD, DD, DD, HH, 0, 0, 0);
            // x += (h @ fc2^T + b2) * ls2
            mma_gemm<EPI_RES, false><<<gFlatD, 256>>>(gh, fc2w + (long)l * DD * HH,
                fc2b + l * DD, ls2 + l * DD, gx,
                Mflat, HH, HH, HH, DD, 0, 0, 0);
        }
    }
    cudaMemcpyAsync(d_out, gx, (size_t)BB * NPTS * DD * sizeof(float),
                    cudaMemcpyDeviceToDevice);
}

// round 7
// speedup vs baseline: 5.2496x; 1.4454x over previous
#include <cuda_runtime.h>
#include <cuda_bf16.h>
#include <math.h>
#include <stdint.h>

#define BB   32
#define NPTS 577
#define DD   384
#define HH   1536
#define LL   12
#define KPAD 640

// ---------------- scratch (device globals; no allocs) ----------------
__device__ __align__(256) float g_x  [BB * NPTS * DD];
__device__ __align__(256) float g_q  [BB * NPTS * DD];
__device__ __align__(256) float g_k  [BB * KPAD * DD];
__device__ __align__(256) float g_tmp[BB * NPTS * DD];
__device__ __align__(256) __nv_bfloat16 b_xn  [BB * NPTS * DD];
__device__ __align__(256) __nv_bfloat16 b_q   [BB * NPTS * DD];
__device__ __align__(256) __nv_bfloat16 b_k   [BB * KPAD * DD];
__device__ __align__(256) __nv_bfloat16 b_mem [BB * KPAD * DD];
__device__ __align__(256) __nv_bfloat16 b_vt  [BB * DD * KPAD];
__device__ __align__(256) __nv_bfloat16 b_attn[BB * NPTS * KPAD];
__device__ __align__(256) __nv_bfloat16 b_tmp [BB * NPTS * DD];
__device__ __align__(256) __nv_bfloat16 b_h   [BB * NPTS * HH];
__device__ __align__(256) __nv_bfloat16 w_qkv [LL * 3 * DD * DD];
__device__ __align__(256) __nv_bfloat16 w_proj[LL * DD * DD];
__device__ __align__(256) __nv_bfloat16 w_fc1 [LL * HH * DD];
__device__ __align__(256) __nv_bfloat16 w_fc2 [LL * DD * HH];

// ---------------- PTX helpers (base ISA only) ----------------
__device__ __forceinline__ void cpa16(uint32_t s, const void* g) {
    asm volatile("cp.async.cg.shared.global [%0], [%1], 16;" :: "r"(s), "l"(g));
}
__device__ __forceinline__ void cpa_commit() {
    asm volatile("cp.async.commit_group;" ::: "memory");
}
__device__ __forceinline__ void ldm4(uint32_t* r, uint32_t addr) {
    asm volatile("ldmatrix.sync.aligned.m8n8.x4.shared.b16 {%0,%1,%2,%3}, [%4];"
        : "=r"(r[0]), "=r"(r[1]), "=r"(r[2]), "=r"(r[3]) : "r"(addr));
}
__device__ __forceinline__ void ldm2(uint32_t* r, uint32_t addr) {
    asm volatile("ldmatrix.sync.aligned.m8n8.x2.shared.b16 {%0,%1}, [%2];"
        : "=r"(r[0]), "=r"(r[1]) : "r"(addr));
}
__device__ __forceinline__ void mma16816(float* c, const uint32_t* a, const uint32_t* b) {
    asm volatile("mma.sync.aligned.m16n8k16.row.col.f32.bf16.bf16.f32 "
        "{%0,%1,%2,%3}, {%4,%5,%6,%7}, {%8,%9}, {%0,%1,%2,%3};"
        : "+f"(c[0]), "+f"(c[1]), "+f"(c[2]), "+f"(c[3])
        : "r"(a[0]), "r"(a[1]), "r"(a[2]), "r"(a[3]), "r"(b[0]), "r"(b[1]));
}

// ---------------- elementwise kernels ----------------
__global__ void f2bf(const float* __restrict__ in, __nv_bfloat16* __restrict__ out, int n) {
    int i = (blockIdx.x * 256 + threadIdx.x) * 4;
    if (i >= n) return;
    float4 v = *(const float4*)(in + i);
    __nv_bfloat162 p0 = __floats2bfloat162_rn(v.x, v.y);
    __nv_bfloat162 p1 = __floats2bfloat162_rn(v.z, v.w);
    *(uint2*)(out + i) = make_uint2(*(uint32_t*)&p0, *(uint32_t*)&p1);
}

__global__ void build_x_mem(const float* __restrict__ inp, float* __restrict__ x,
                            __nv_bfloat16* __restrict__ mem, int r) {
    int d = threadIdx.x, n = blockIdx.x, b = blockIdx.y;
    long xi = ((long)b * NPTS + n) * DD + d;
    long mi = ((long)b * KPAD + n) * DD + d;
    if (n == 0) {
        float val = (r == 0) ? inp[xi] : x[xi];
        x[xi] = val;
        __nv_bfloat16 bv = __float2bfloat16(val);
        mem[mi] = bv;
        mem[((long)b * KPAD + NPTS + r) * DD + d] = bv;
    } else {
        float val = inp[xi];
        x[xi] = val;
        mem[mi] = __float2bfloat16(val);
    }
}

// warp-per-row LN, fp32 in -> bf16 out, optional extra scale folded in
__global__ void ln_bf16(const float* __restrict__ in, const float* __restrict__ w,
                        const float* __restrict__ b, __nv_bfloat16* __restrict__ out,
                        int rows, long strIn, long strOut, float scale) {
    int warp = threadIdx.x >> 5, lane = threadIdx.x & 31;
    int row = blockIdx.x * 8 + warp;
    if (row >= rows) return;
    const float* x = in + (long)blockIdx.y * strIn + (long)row * DD;
    __nv_bfloat16* y = out + (long)blockIdx.y * strOut + (long)row * DD;
    float4 v[3]; float s = 0.f;
    #pragma unroll
    for (int j = 0; j < 3; j++) {
        v[j] = *(const float4*)(x + lane * 4 + j * 128);
        s += (v[j].x + v[j].y) + (v[j].z + v[j].w);
    }
    #pragma unroll
    for (int o = 16; o; o >>= 1) s += __shfl_xor_sync(~0u, s, o);
    float mu = s * (1.f / 384.f), q = 0.f;
    #pragma unroll
    for (int j = 0; j < 3; j++) {
        v[j].x -= mu; v[j].y -= mu; v[j].z -= mu; v[j].w -= mu;
        q += v[j].x * v[j].x + v[j].y * v[j].y + v[j].z * v[j].z + v[j].w * v[j].w;
    }
    #pragma unroll
    for (int o = 16; o; o >>= 1) q += __shfl_xor_sync(~0u, q, o);
    float rs = rsqrtf(q * (1.f / 384.f) + 1e-6f);
    #pragma unroll
    for (int j = 0; j < 3; j++) {
        int c = lane * 4 + j * 128;
        float4 wv = *(const float4*)(w + c);
        float4 bv = *(const float4*)(b + c);
        __nv_bfloat162 p0 = __floats2bfloat162_rn((v[j].x * rs * wv.x + bv.x) * scale,
                                                  (v[j].y * rs * wv.y + bv.y) * scale);
        __nv_bfloat162 p1 = __floats2bfloat162_rn((v[j].z * rs * wv.z + bv.z) * scale,
                                                  (v[j].w * rs * wv.w + bv.w) * scale);
        *(uint2*)(y + c) = make_uint2(*(uint32_t*)&p0, *(uint32_t*)&p1);
    }
}

__global__ void softmax_bf16(__nv_bfloat16* __restrict__ attn, int Mc) {
    __shared__ float red[8];
    __nv_bfloat16* row = attn + ((long)blockIdx.y * NPTS + blockIdx.x) * KPAD;
    int t = threadIdx.x;
    float v[3], mx = -3.0e38f;
    #pragma unroll
    for (int i = 0; i < 3; i++) {
        int c = t + i * 256;
        v[i] = (c < Mc) ? __bfloat162float(row[c]) : -3.0e38f;
        mx = fmaxf(mx, v[i]);
    }
    #pragma unroll
    for (int o = 16; o; o >>= 1) mx = fmaxf(mx, __shfl_xor_sync(~0u, mx, o));
    if ((t & 31) == 0) red[t >> 5] = mx;
    __syncthreads();
    mx = red[0];
    #pragma unroll
    for (int i = 1; i < 8; i++) mx = fmaxf(mx, red[i]);
    float s = 0.f;
    #pragma unroll
    for (int i = 0; i < 3; i++) {
        int c = t + i * 256;
        v[i] = (c < Mc) ? expf(v[i] - mx) : 0.f;
        s += v[i];
    }
    #pragma unroll
    for (int o = 16; o; o >>= 1) s += __shfl_xor_sync(~0u, s, o);
    __syncthreads();
    if ((t & 31) == 0) red[t >> 5] = s;
    __syncthreads();
    s = red[0] + red[1] + red[2] + red[3] + red[4] + red[5] + red[6] + red[7];
    float inv = 1.f / s;
    #pragma unroll
    for (int i = 0; i < 3; i++) {
        int c = t + i * 256;
        if (c < KPAD) row[c] = __float2bfloat16(v[i] * inv);
    }
}

// ---------------- mma.sync bf16 GEMM, cp.async double-buffered ----------------
// C[m,n] = sum_k A[m,k]*B[n,k], A/B bf16 K-major. BM=BN=128, BK=32, 256 thr.
// K % 32 == 0; N tile rows must exist (pad rows allowed); M guarded.
#define BM 128
#define BN 128
#define SROWB 80     // 32 bf16 = 64B data + 16B pad; cp.async dst 16B aligned; conflict-free
#define STGB ((BM + BN) * SROWB)   // 20480 bytes per stage

#define EPI_QK    0   // +bias -> fp32
#define EPI_VT    1   // +bias -> bf16 transposed
#define EPI_LOGIT 2   // plain -> bf16
#define EPI_AV    3   // plain -> fp32
#define EPI_GELU  4   // +bias, gelu -> bf16
#define EPI_RES   5   // (acc+bias)*ls + C -> fp32

template<int EPI>
__global__ void __launch_bounds__(256, 2)
mma_gemm(const __nv_bfloat16* __restrict__ A, const __nv_bfloat16* __restrict__ B,
         const float* __restrict__ bias, const float* __restrict__ ls,
         void* __restrict__ Cv,
         int M, int K, int lda, int ldb, int ldc,
         long strA, long strB, long strC)
{
    __shared__ __align__(16) char smem_[2 * STGB];
    A += (long)blockIdx.z * strA;
    B += (long)blockIdx.z * strB;
    int m0 = blockIdx.y * BM, n0 = blockIdx.x * BN;
    int t = threadIdx.x;
    int warp = t >> 5, lane = t & 31;
    int wm = warp & 1, wn = warp >> 1;

    float acc[4][4][4];
    #pragma unroll
    for (int i = 0; i < 4; i++)
        #pragma unroll
        for (int j = 0; j < 4; j++)
            #pragma unroll
            for (int q = 0; q < 4; q++) acc[i][j][q] = 0.f;

    uint32_t sb = (uint32_t)__cvta_generic_to_shared(smem_);

    // staging: 256 threads x 2 chunks for A (512 = 128 rows x 4 x 16B), same for B
    int sRow = t >> 2;          // chunk row contribution base
    int sCol = (t & 3) * 16;    // byte column within row (0,16,32,48)
    auto stage = [&](int kt) {
        uint32_t tA = sb + (uint32_t)((kt & 1) * STGB);
        uint32_t tB = tA + BM * SROWB;
        int k0 = kt * 32;
        #pragma unroll
        for (int i2 = 0; i2 < 2; i2++) {
            int row = sRow + i2 * 64;
            int gm = m0 + row; gm = gm < M ? gm : M - 1;     // clamp; masked at store
            cpa16(tA + (uint32_t)(row * SROWB + sCol), A + (long)gm * lda + k0 + sCol / 2);
        }
        #pragma unroll
        for (int i2 = 0; i2 < 2; i2++) {
            int row = sRow + i2 * 64;
            cpa16(tB + (uint32_t)(row * SROWB + sCol), B + (long)(n0 + row) * ldb + k0 + sCol / 2);
        }
        cpa_commit();
    };

    const int T = K >> 5;
    stage(0);
    stage(1);

    uint32_t aOff = (uint32_t)((wm * 64 + (lane & 15)) * SROWB + (lane >> 4) * 16);
    uint32_t bOff = (uint32_t)(BM * SROWB + (wn * 32 + (lane & 7)) * SROWB + ((lane >> 3) & 1) * 16);

    for (int i = 0; i < T; i++) {
        asm volatile("cp.async.wait_group 1;" ::: "memory");
        __syncthreads();
        uint32_t tbase = sb + (uint32_t)((i & 1) * STGB);
        #pragma unroll
        for (int kk = 0; kk < 2; kk++) {
            uint32_t af[4][4], bf_[4][2];
            #pragma unroll
            for (int mt = 0; mt < 4; mt++)
                ldm4(af[mt], tbase + aOff + (uint32_t)(mt * 16 * SROWB + kk * 32));
            #pragma unroll
            for (int nt = 0; nt < 4; nt++)
                ldm2(bf_[nt], tbase + bOff + (uint32_t)(nt * 8 * SROWB + kk * 32));
            #pragma unroll
            for (int mt = 0; mt < 4; mt++)
                #pragma unroll
                for (int nt = 0; nt < 4; nt++)
                    mma16816(acc[mt][nt], af[mt], bf_[nt]);
        }
        __syncthreads();
        if (i + 2 < T) stage(i + 2);
        else cpa_commit();           // keep wait_group counting aligned
    }

    // ---- epilogue ----
    int g = lane >> 2, tg = lane & 3;
    #pragma unroll
    for (int mt = 0; mt < 4; mt++) {
        #pragma unroll
        for (int nt = 0; nt < 4; nt++) {
            int gm = m0 + wm * 64 + mt * 16 + g;
            int gn = n0 + wn * 32 + nt * 8 + tg * 2;
            float* cc = acc[mt][nt];
            float b0 = 0.f, b1 = 0.f, l0 = 0.f, l1 = 0.f;
            if (EPI == EPI_QK || EPI == EPI_VT || EPI == EPI_GELU || EPI == EPI_RES) {
                float2 bv = *(const float2*)&bias[gn]; b0 = bv.x; b1 = bv.y;
            }
            if (EPI == EPI_RES) { float2 lv = *(const float2*)&ls[gn]; l0 = lv.x; l1 = lv.y; }
            #pragma unroll
            for (int h = 0; h < 2; h++) {
                int gmh = gm + h * 8;
                if (gmh >= M) continue;
                float v0 = cc[h * 2 + 0], v1 = cc[h * 2 + 1];
                if (EPI == EPI_QK) {
                    float* C = (float*)Cv + (long)blockIdx.z * strC;
                    *(float2*)&C[(long)gmh * ldc + gn] = make_float2(v0 + b0, v1 + b1);
                } else if (EPI == EPI_AV) {
                    float* C = (float*)Cv + (long)blockIdx.z * strC;
                    *(float2*)&C[(long)gmh * ldc + gn] = make_float2(v0, v1);
                } else if (EPI == EPI_RES) {
                    float* C = (float*)Cv + (long)blockIdx.z * strC;
                    long ci = (long)gmh * ldc + gn;
                    float2 old = *(float2*)&C[ci];
                    *(float2*)&C[ci] = make_float2((v0 + b0) * l0 + old.x,
                                                   (v1 + b1) * l1 + old.y);
                } else if (EPI == EPI_GELU) {
                    __nv_bfloat16* C = (__nv_bfloat16*)Cv + (long)blockIdx.z * strC;
                    v0 += b0; v1 += b1;
                    v0 = 0.5f * v0 * (1.f + erff(v0 * 0.70710678118654752f));
                    v1 = 0.5f * v1 * (1.f + erff(v1 * 0.70710678118654752f));
                    __nv_bfloat162 p = __floats2bfloat162_rn(v0, v1);
                    *(uint32_t*)&C[(long)gmh * ldc + gn] = *(uint32_t*)&p;
                } else if (EPI == EPI_LOGIT) {
                    __nv_bfloat16* C = (__nv_bfloat16*)Cv + (long)blockIdx.z * strC;
                    __nv_bfloat162 p = __floats2bfloat162_rn(v0, v1);
                    *(uint32_t*)&C[(long)gmh * ldc + gn] = *(uint32_t*)&p;
                } else {   // EPI_VT: transposed bf16 store
                    __nv_bfloat16* C = (__nv_bfloat16*)Cv + (long)blockIdx.z * strC;
                    C[(long)gn * ldc + gmh]       = __float2bfloat16(v0 + b0);
                    C[(long)(gn + 1) * ldc + gmh] = __float2bfloat16(v1 + b1);
                }
            }
        }
    }
}

// ---------------- host ----------------
extern "C" void kernel_launch(void* const* d_in, const int* in_sizes, int n_in,
                              void* d_out, int out_size)
{
    const float* x_in = (const float*)d_in[0];
    const float* n1w = (const float*)d_in[1];  const float* n1b = (const float*)d_in[2];
    const float* qkvw = (const float*)d_in[3]; const float* qkvb = (const float*)d_in[4];
    const float* qnw = (const float*)d_in[5];  const float* qnb = (const float*)d_in[6];
    const float* knw = (const float*)d_in[7];  const float* knb = (const float*)d_in[8];
    const float* anw = (const float*)d_in[9];  const float* anb = (const float*)d_in[10];
    const float* projw = (const float*)d_in[11]; const float* projb = (const float*)d_in[12];
    const float* ls1 = (const float*)d_in[13];
    const float* n2w = (const float*)d_in[14]; const float* n2b = (const float*)d_in[15];
    const float* fc1w = (const float*)d_in[16]; const float* fc1b = (const float*)d_in[17];
    const float* fc2w = (const float*)d_in[18]; const float* fc2b = (const float*)d_in[19];
    const float* ls2 = (const float*)d_in[20];

    float *gx, *gq, *gk, *gtmp;
    __nv_bfloat16 *bxn, *bq, *bk, *bmem, *bvt, *battn, *btmp, *bh, *wq, *wp, *w1, *w2;
    cudaGetSymbolAddress((void**)&gx, g_x);    cudaGetSymbolAddress((void**)&gq, g_q);
    cudaGetSymbolAddress((void**)&gk, g_k);    cudaGetSymbolAddress((void**)&gtmp, g_tmp);
    cudaGetSymbolAddress((void**)&bxn, b_xn);  cudaGetSymbolAddress((void**)&bq, b_q);
    cudaGetSymbolAddress((void**)&bk, b_k);    cudaGetSymbolAddress((void**)&bmem, b_mem);
    cudaGetSymbolAddress((void**)&bvt, b_vt);  cudaGetSymbolAddress((void**)&battn, b_attn);
    cudaGetSymbolAddress((void**)&btmp, b_tmp);cudaGetSymbolAddress((void**)&bh, b_h);
    cudaGetSymbolAddress((void**)&wq, w_qkv);  cudaGetSymbolAddress((void**)&wp, w_proj);
    cudaGetSymbolAddress((void**)&w1, w_fc1);  cudaGetSymbolAddress((void**)&w2, w_fc2);

    int n;
    n = LL * 3 * DD * DD; f2bf<<<(n / 4 + 255) / 256, 256>>>(qkvw, wq, n);
    n = LL * DD * DD;     f2bf<<<(n / 4 + 255) / 256, 256>>>(projw, wp, n);
    n = LL * HH * DD;     f2bf<<<(n / 4 + 255) / 256, 256>>>(fc1w, w1, n);
    n = LL * DD * HH;     f2bf<<<(n / 4 + 255) / 256, 256>>>(fc2w, w2, n);

    const float scale = 1.0f / sqrtf((float)DD);
    const long xS = (long)NPTS * DD, mS = (long)KPAD * DD;
    const long vtS = (long)DD * KPAD, aS = (long)NPTS * KPAD;
    const int Mflat = BB * NPTS;                 // 18464
    const dim3 gFlatD(3, 145, 1), gFlatH(12, 145, 1);

    for (int r = 0; r < 4; r++) {
        int curM = NPTS + r;
        build_x_mem<<<dim3(NPTS, BB), DD>>>(x_in, gx, bmem, r);
        for (int l = 0; l < LL; l++) {
            const __nv_bfloat16* Wq = wq + (long)l * 3 * DD * DD;
            const __nv_bfloat16* Wk = Wq + (long)DD * DD;
            const __nv_bfloat16* Wv = Wk + (long)DD * DD;
            const float* bqp = qkvb + (long)l * 3 * DD;
            const float* bkp = bqp + DD;
            const float* bvp = bkp + DD;

            // xn = LN(x, norm1) -> bf16
            ln_bf16<<<2308, 256>>>(gx, n1w + l * DD, n1b + l * DD, bxn, Mflat, 0, 0, 1.f);
            // q = xn @ Wq^T + bq -> fp32 ; then q-LN (scale folded) -> bf16
            mma_gemm<EPI_QK><<<gFlatD, 256>>>(bxn, Wq, bqp, nullptr, gq,
                Mflat, DD, DD, DD, DD, 0, 0, 0);
            ln_bf16<<<2308, 256>>>(gq, qnw + l * DD, qnb + l * DD, bq, Mflat, 0, 0, scale);
            // k = mem @ Wk^T + bk -> fp32 ; k-LN -> bf16  (batched over BB)
            dim3 gKV(3, 5, BB);
            mma_gemm<EPI_QK><<<gKV, 256>>>(bmem, Wk, bkp, nullptr, gk,
                curM, DD, DD, DD, DD, mS, 0, mS);
            ln_bf16<<<dim3((curM + 7) / 8, BB), 256>>>(gk, knw + l * DD, knb + l * DD, bk,
                curM, mS, mS, 1.f);
            // vT = (mem @ Wv^T + bv)^T -> bf16 [d][mem]
            mma_gemm<EPI_VT><<<gKV, 256>>>(bmem, Wv, bvp, nullptr, bvt,
                curM, DD, DD, DD, KPAD, mS, 0, vtS);
            // logits = q_scaled @ k^T -> bf16 (pad cols handled by softmax mask)
            dim3 gLog(5, 5, BB);
            mma_gemm<EPI_LOGIT><<<gLog, 256>>>(bq, bk, nullptr, nullptr, battn,
                NPTS, DD, DD, DD, KPAD, xS, mS, aS);
            softmax_bf16<<<dim3(NPTS, BB), 256>>>(battn, curM);
            // prod = attn @ vT^T -> fp32 (attn pad cols are exact zeros)
            dim3 gProd(3, 5, BB);
            mma_gemm<EPI_AV><<<gProd, 256>>>(battn, bvt, nullptr, nullptr, gtmp,
                NPTS, KPAD, KPAD, KPAD, DD, aS, vtS, xS);
            // an-LN -> bf16
            ln_bf16<<<dim3((NPTS + 7) / 8, BB), 256>>>(gtmp, anw + l * DD, anb + l * DD, btmp,
                NPTS, xS, xS, 1.f);
            // x += (prodn @ proj^T + pb) * ls1
            mma_gemm<EPI_RES><<<gFlatD, 256>>>(btmp, wp + (long)l * DD * DD,
                projb + l * DD, ls1 + l * DD, gx, Mflat, DD, DD, DD, DD, 0, 0, 0);
            // norm2 -> bf16
            ln_bf16<<<2308, 256>>>(gx, n2w + l * DD, n2b + l * DD, bxn, Mflat, 0, 0, 1.f);
            // h = gelu(xn @ fc1^T + b1) -> bf16
            mma_gemm<EPI_GELU><<<gFlatH, 256>>>(bxn, w1 + (long)l * HH * DD,
                fc1b + (long)l * HH, nullptr, bh, Mflat, DD, DD, DD, HH, 0, 0, 0);
            // x += (h @ fc2^T + b2) * ls2
            mma_gemm<EPI_RES><<<gFlatD, 256>>>(bh, w2 + (long)l * DD * HH,
                fc2b + l * DD, ls2 + l * DD, gx, Mflat, HH, HH, HH, DD, 0, 0, 0);
        }
    }
    cudaMemcpyAsync(d_out, gx, (size_t)BB * NPTS * DD * sizeof(float),
                    cudaMemcpyDeviceToDevice);
}

// round 8
// speedup vs baseline: 5.5172x; 1.0510x over previous
#include <cuda_runtime.h>
#include <cuda_bf16.h>
#include <math.h>
#include <stdint.h>

#define BB   32
#define NPTS 577
#define DD   384
#define HH   1536
#define LL   12
#define KPAD 640

// ---------------- scratch (device globals; no allocs) ----------------
__device__ __align__(256) float g_x  [BB * NPTS * DD];
__device__ __align__(256) float g_q  [BB * NPTS * DD];
__device__ __align__(256) float g_k  [BB * KPAD * DD];
__device__ __align__(256) float g_tmp[BB * NPTS * DD];
__device__ __align__(256) __nv_bfloat16 b_xn  [BB * NPTS * DD];
__device__ __align__(256) __nv_bfloat16 b_q   [BB * NPTS * DD];
__device__ __align__(256) __nv_bfloat16 b_k   [BB * KPAD * DD];
__device__ __align__(256) __nv_bfloat16 b_mem [BB * KPAD * DD];
__device__ __align__(256) __nv_bfloat16 b_vt  [BB * DD * KPAD];
__device__ __align__(256) __nv_bfloat16 b_attn[BB * NPTS * KPAD];
__device__ __align__(256) __nv_bfloat16 b_tmp [BB * NPTS * DD];
__device__ __align__(256) __nv_bfloat16 b_h   [BB * NPTS * HH];
__device__ __align__(256) __nv_bfloat16 w_qkv [LL * 3 * DD * DD];
__device__ __align__(256) __nv_bfloat16 w_proj[LL * DD * DD];
__device__ __align__(256) __nv_bfloat16 w_fc1 [LL * HH * DD];
__device__ __align__(256) __nv_bfloat16 w_fc2 [LL * DD * HH];

// ---------------- PTX helpers (base ISA only) ----------------
__device__ __forceinline__ void cpa16(uint32_t s, const void* g) {
    asm volatile("cp.async.cg.shared.global [%0], [%1], 16;" :: "r"(s), "l"(g));
}
__device__ __forceinline__ void cpa_commit() {
    asm volatile("cp.async.commit_group;" ::: "memory");
}
__device__ __forceinline__ void ldm4(uint32_t* r, uint32_t addr) {
    asm volatile("ldmatrix.sync.aligned.m8n8.x4.shared.b16 {%0,%1,%2,%3}, [%4];"
        : "=r"(r[0]), "=r"(r[1]), "=r"(r[2]), "=r"(r[3]) : "r"(addr));
}
__device__ __forceinline__ void ldm2(uint32_t* r, uint32_t addr) {
    asm volatile("ldmatrix.sync.aligned.m8n8.x2.shared.b16 {%0,%1}, [%2];"
        : "=r"(r[0]), "=r"(r[1]) : "r"(addr));
}
__device__ __forceinline__ void mma16816(float* c, const uint32_t* a, const uint32_t* b) {
    asm volatile("mma.sync.aligned.m16n8k16.row.col.f32.bf16.bf16.f32 "
        "{%0,%1,%2,%3}, {%4,%5,%6,%7}, {%8,%9}, {%0,%1,%2,%3};"
        : "+f"(c[0]), "+f"(c[1]), "+f"(c[2]), "+f"(c[3])
        : "r"(a[0]), "r"(a[1]), "r"(a[2]), "r"(a[3]), "r"(b[0]), "r"(b[1]));
}

// ---------------- elementwise kernels ----------------
__global__ void f2bf(const float* __restrict__ in, __nv_bfloat16* __restrict__ out, int n) {
    int i = (blockIdx.x * 256 + threadIdx.x) * 4;
    if (i >= n) return;
    float4 v = *(const float4*)(in + i);
    __nv_bfloat162 p0 = __floats2bfloat162_rn(v.x, v.y);
    __nv_bfloat162 p1 = __floats2bfloat162_rn(v.z, v.w);
    *(uint2*)(out + i) = make_uint2(*(uint32_t*)&p0, *(uint32_t*)&p1);
}

__global__ void build_x_mem(const float* __restrict__ inp, float* __restrict__ x,
                            __nv_bfloat16* __restrict__ mem, int r) {
    int d = threadIdx.x, n = blockIdx.x, b = blockIdx.y;
    long xi = ((long)b * NPTS + n) * DD + d;
    long mi = ((long)b * KPAD + n) * DD + d;
    if (n == 0) {
        float val = (r == 0) ? inp[xi] : x[xi];
        x[xi] = val;
        __nv_bfloat16 bv = __float2bfloat16(val);
        mem[mi] = bv;
        mem[((long)b * KPAD + NPTS + r) * DD + d] = bv;
    } else {
        float val = inp[xi];
        x[xi] = val;
        mem[mi] = __float2bfloat16(val);
    }
}

// warp-per-row LN, fp32 in -> bf16 out, optional extra scale folded in
__global__ void ln_bf16(const float* __restrict__ in, const float* __restrict__ w,
                        const float* __restrict__ b, __nv_bfloat16* __restrict__ out,
                        int rows, long strIn, long strOut, float scale) {
    int warp = threadIdx.x >> 5, lane = threadIdx.x & 31;
    int row = blockIdx.x * 8 + warp;
    if (row >= rows) return;
    const float* x = in + (long)blockIdx.y * strIn + (long)row * DD;
    __nv_bfloat16* y = out + (long)blockIdx.y * strOut + (long)row * DD;
    float4 v[3]; float s = 0.f;
    #pragma unroll
    for (int j = 0; j < 3; j++) {
        v[j] = *(const float4*)(x + lane * 4 + j * 128);
        s += (v[j].x + v[j].y) + (v[j].z + v[j].w);
    }
    #pragma unroll
    for (int o = 16; o; o >>= 1) s += __shfl_xor_sync(~0u, s, o);
    float mu = s * (1.f / 384.f), q = 0.f;
    #pragma unroll
    for (int j = 0; j < 3; j++) {
        v[j].x -= mu; v[j].y -= mu; v[j].z -= mu; v[j].w -= mu;
        q += v[j].x * v[j].x + v[j].y * v[j].y + v[j].z * v[j].z + v[j].w * v[j].w;
    }
    #pragma unroll
    for (int o = 16; o; o >>= 1) q += __shfl_xor_sync(~0u, q, o);
    float rs = rsqrtf(q * (1.f / 384.f) + 1e-6f);
    #pragma unroll
    for (int j = 0; j < 3; j++) {
        int c = lane * 4 + j * 128;
        float4 wv = *(const float4*)(w + c);
        float4 bv = *(const float4*)(b + c);
        __nv_bfloat162 p0 = __floats2bfloat162_rn((v[j].x * rs * wv.x + bv.x) * scale,
                                                  (v[j].y * rs * wv.y + bv.y) * scale);
        __nv_bfloat162 p1 = __floats2bfloat162_rn((v[j].z * rs * wv.z + bv.z) * scale,
                                                  (v[j].w * rs * wv.w + bv.w) * scale);
        *(uint2*)(y + c) = make_uint2(*(uint32_t*)&p0, *(uint32_t*)&p1);
    }
}

__global__ void softmax_bf16(__nv_bfloat16* __restrict__ attn, int Mc) {
    __shared__ float red[8];
    __nv_bfloat16* row = attn + ((long)blockIdx.y * NPTS + blockIdx.x) * KPAD;
    int t = threadIdx.x;
    float v[3], mx = -3.0e38f;
    #pragma unroll
    for (int i = 0; i < 3; i++) {
        int c = t + i * 256;
        v[i] = (c < Mc) ? __bfloat162float(row[c]) : -3.0e38f;
        mx = fmaxf(mx, v[i]);
    }
    #pragma unroll
    for (int o = 16; o; o >>= 1) mx = fmaxf(mx, __shfl_xor_sync(~0u, mx, o));
    if ((t & 31) == 0) red[t >> 5] = mx;
    __syncthreads();
    mx = red[0];
    #pragma unroll
    for (int i = 1; i < 8; i++) mx = fmaxf(mx, red[i]);
    float s = 0.f;
    #pragma unroll
    for (int i = 0; i < 3; i++) {
        int c = t + i * 256;
        v[i] = (c < Mc) ? expf(v[i] - mx) : 0.f;
        s += v[i];
    }
    #pragma unroll
    for (int o = 16; o; o >>= 1) s += __shfl_xor_sync(~0u, s, o);
    __syncthreads();
    if ((t & 31) == 0) red[t >> 5] = s;
    __syncthreads();
    s = red[0] + red[1] + red[2] + red[3] + red[4] + red[5] + red[6] + red[7];
    float inv = 1.f / s;
    #pragma unroll
    for (int i = 0; i < 3; i++) {
        int c = t + i * 256;
        if (c < KPAD) row[c] = __float2bfloat16(v[i] * inv);
    }
}

// ---------------- mma.sync bf16 GEMM, 3-stage cp.async pipeline ----------------
// C[m,n] = sum_k A[m,k]*B[n,k], A/B bf16 K-major. BM=BN=128, BK=32, 256 thr.
#define BM 128
#define BN 128
#define SROWB 80
#define STGB ((BM + BN) * SROWB)   // 20480 bytes per stage
#define NSTAGE 3
#define SMEMB (NSTAGE * STGB)      // 61440

#define EPI_QK    0   // +bias -> fp32
#define EPI_KV    1   // cols<384: +bias -> fp32 k ; cols>=384: +bias -> bf16 vt transposed
#define EPI_LOGIT 2   // plain -> bf16
#define EPI_AV    3   // plain -> fp32
#define EPI_GELU  4   // +bias, gelu -> bf16
#define EPI_RES   5   // (acc+bias)*ls + C -> fp32

template<int EPI>
__global__ void __launch_bounds__(256, 2)
mma_gemm(const __nv_bfloat16* __restrict__ A, const __nv_bfloat16* __restrict__ B,
         const float* __restrict__ bias, const float* __restrict__ ls,
         void* __restrict__ Cv, void* __restrict__ Cv2,
         int M, int K, int lda, int ldb, int ldc, int ldc2,
         long strA, long strB, long strC, long strC2)
{
    extern __shared__ __align__(16) char smem_[];
    A += (long)blockIdx.z * strA;
    B += (long)blockIdx.z * strB;
    int m0 = blockIdx.y * BM, n0 = blockIdx.x * BN;
    int t = threadIdx.x;
    int warp = t >> 5, lane = t & 31;
    int wm = warp & 1, wn = warp >> 1;

    float acc[4][4][4];
    #pragma unroll
    for (int i = 0; i < 4; i++)
        #pragma unroll
        for (int j = 0; j < 4; j++)
            #pragma unroll
            for (int q = 0; q < 4; q++) acc[i][j][q] = 0.f;

    uint32_t sb = (uint32_t)__cvta_generic_to_shared(smem_);

    int sRow = t >> 2;
    int sCol = (t & 3) * 16;
    auto stage = [&](int kt) {
        uint32_t tA = sb + (uint32_t)((kt % NSTAGE) * STGB);
        uint32_t tB = tA + BM * SROWB;
        int k0 = kt * 32;
        #pragma unroll
        for (int i2 = 0; i2 < 2; i2++) {
            int row = sRow + i2 * 64;
            int gm = m0 + row; gm = gm < M ? gm : M - 1;
            cpa16(tA + (uint32_t)(row * SROWB + sCol), A + (long)gm * lda + k0 + sCol / 2);
        }
        #pragma unroll
        for (int i2 = 0; i2 < 2; i2++) {
            int row = sRow + i2 * 64;
            cpa16(tB + (uint32_t)(row * SROWB + sCol), B + (long)(n0 + row) * ldb + k0 + sCol / 2);
        }
        cpa_commit();
    };

    const int T = K >> 5;
    stage(0);
    stage(1);

    uint32_t aOff = (uint32_t)((wm * 64 + (lane & 15)) * SROWB + (lane >> 4) * 16);
    uint32_t bOff = (uint32_t)(BM * SROWB + (wn * 32 + (lane & 7)) * SROWB + ((lane >> 3) & 1) * 16);

    for (int i = 0; i < T; i++) {
        asm volatile("cp.async.wait_group 1;" ::: "memory");
        __syncthreads();
        if (i + 2 < T) stage(i + 2);     // keep 2 loads in flight during compute
        else cpa_commit();
        uint32_t tbase = sb + (uint32_t)((i % NSTAGE) * STGB);
        #pragma unroll
        for (int kk = 0; kk < 2; kk++) {
            uint32_t af[4][4], bf_[4][2];
            #pragma unroll
            for (int mt = 0; mt < 4; mt++)
                ldm4(af[mt], tbase + aOff + (uint32_t)(mt * 16 * SROWB + kk * 32));
            #pragma unroll
            for (int nt = 0; nt < 4; nt++)
                ldm2(bf_[nt], tbase + bOff + (uint32_t)(nt * 8 * SROWB + kk * 32));
            #pragma unroll
            for (int mt = 0; mt < 4; mt++)
                #pragma unroll
                for (int nt = 0; nt < 4; nt++)
                    mma16816(acc[mt][nt], af[mt], bf_[nt]);
        }
        __syncthreads();
    }

    // ---- epilogue ----
    int g = lane >> 2, tg = lane & 3;
    #pragma unroll
    for (int mt = 0; mt < 4; mt++) {
        #pragma unroll
        for (int nt = 0; nt < 4; nt++) {
            int gm = m0 + wm * 64 + mt * 16 + g;
            int gn = n0 + wn * 32 + nt * 8 + tg * 2;
            float* cc = acc[mt][nt];
            float b0 = 0.f, b1 = 0.f, l0 = 0.f, l1 = 0.f;
            if (EPI == EPI_QK || EPI == EPI_KV || EPI == EPI_GELU || EPI == EPI_RES) {
                float2 bv = *(const float2*)&bias[gn]; b0 = bv.x; b1 = bv.y;
            }
            if (EPI == EPI_RES) { float2 lv = *(const float2*)&ls[gn]; l0 = lv.x; l1 = lv.y; }
            #pragma unroll
            for (int h = 0; h < 2; h++) {
                int gmh = gm + h * 8;
                if (gmh >= M) continue;
                float v0 = cc[h * 2 + 0], v1 = cc[h * 2 + 1];
                if (EPI == EPI_QK) {
                    float* C = (float*)Cv + (long)blockIdx.z * strC;
                    *(float2*)&C[(long)gmh * ldc + gn] = make_float2(v0 + b0, v1 + b1);
                } else if (EPI == EPI_KV) {
                    if (gn < DD) {   // k path: fp32
                        float* C = (float*)Cv + (long)blockIdx.z * strC;
                        *(float2*)&C[(long)gmh * ldc + gn] = make_float2(v0 + b0, v1 + b1);
                    } else {         // v path: transposed bf16
                        __nv_bfloat16* C2 = (__nv_bfloat16*)Cv2 + (long)blockIdx.z * strC2;
                        int vn = gn - DD;
                        C2[(long)vn * ldc2 + gmh]       = __float2bfloat16(v0 + b0);
                        C2[(long)(vn + 1) * ldc2 + gmh] = __float2bfloat16(v1 + b1);
                    }
                } else if (EPI == EPI_AV) {
                    float* C = (float*)Cv + (long)blockIdx.z * strC;
                    *(float2*)&C[(long)gmh * ldc + gn] = make_float2(v0, v1);
                } else if (EPI == EPI_RES) {
                    float* C = (float*)Cv + (long)blockIdx.z * strC;
                    long ci = (long)gmh * ldc + gn;
                    float2 old = *(float2*)&C[ci];
                    *(float2*)&C[ci] = make_float2((v0 + b0) * l0 + old.x,
                                                   (v1 + b1) * l1 + old.y);
                } else if (EPI == EPI_GELU) {
                    __nv_bfloat16* C = (__nv_bfloat16*)Cv + (long)blockIdx.z * strC;
                    v0 += b0; v1 += b1;
                    v0 = 0.5f * v0 * (1.f + erff(v0 * 0.70710678118654752f));
                    v1 = 0.5f * v1 * (1.f + erff(v1 * 0.70710678118654752f));
                    __nv_bfloat162 p = __floats2bfloat162_rn(v0, v1);
                    *(uint32_t*)&C[(long)gmh * ldc + gn] = *(uint32_t*)&p;
                } else {   // EPI_LOGIT
                    __nv_bfloat16* C = (__nv_bfloat16*)Cv + (long)blockIdx.z * strC;
                    __nv_bfloat162 p = __floats2bfloat162_rn(v0, v1);
                    *(uint32_t*)&C[(long)gmh * ldc + gn] = *(uint32_t*)&p;
                }
            }
        }
    }
}

// ---------------- host ----------------
extern "C" void kernel_launch(void* const* d_in, const int* in_sizes, int n_in,
                              void* d_out, int out_size)
{
    const float* x_in = (const float*)d_in[0];
    const float* n1w = (const float*)d_in[1];  const float* n1b = (const float*)d_in[2];
    const float* qkvw = (const float*)d_in[3]; const float* qkvb = (const float*)d_in[4];
    const float* qnw = (const float*)d_in[5];  const float* qnb = (const float*)d_in[6];
    const float* knw = (const float*)d_in[7];  const float* knb = (const float*)d_in[8];
    const float* anw = (const float*)d_in[9];  const float* anb = (const float*)d_in[10];
    const float* projw = (const float*)d_in[11]; const float* projb = (const float*)d_in[12];
    const float* ls1 = (const float*)d_in[13];
    const float* n2w = (const float*)d_in[14]; const float* n2b = (const float*)d_in[15];
    const float* fc1w = (const float*)d_in[16]; const float* fc1b = (const float*)d_in[17];
    const float* fc2w = (const float*)d_in[18]; const float* fc2b = (const float*)d_in[19];
    const float* ls2 = (const float*)d_in[20];

    float *gx, *gq, *gk, *gtmp;
    __nv_bfloat16 *bxn, *bq, *bk, *bmem, *bvt, *battn, *btmp, *bh, *wq, *wp, *w1, *w2;
    cudaGetSymbolAddress((void**)&gx, g_x);    cudaGetSymbolAddress((void**)&gq, g_q);
    cudaGetSymbolAddress((void**)&gk, g_k);    cudaGetSymbolAddress((void**)&gtmp, g_tmp);
    cudaGetSymbolAddress((void**)&bxn, b_xn);  cudaGetSymbolAddress((void**)&bq, b_q);
    cudaGetSymbolAddress((void**)&bk, b_k);    cudaGetSymbolAddress((void**)&bmem, b_mem);
    cudaGetSymbolAddress((void**)&bvt, b_vt);  cudaGetSymbolAddress((void**)&battn, b_attn);
    cudaGetSymbolAddress((void**)&btmp, b_tmp);cudaGetSymbolAddress((void**)&bh, b_h);
    cudaGetSymbolAddress((void**)&wq, w_qkv);  cudaGetSymbolAddress((void**)&wp, w_proj);
    cudaGetSymbolAddress((void**)&w1, w_fc1);  cudaGetSymbolAddress((void**)&w2, w_fc2);

    cudaFuncSetAttribute(mma_gemm<EPI_QK>,    cudaFuncAttributeMaxDynamicSharedMemorySize, SMEMB);
    cudaFuncSetAttribute(mma_gemm<EPI_KV>,    cudaFuncAttributeMaxDynamicSharedMemorySize, SMEMB);
    cudaFuncSetAttribute(mma_gemm<EPI_LOGIT>, cudaFuncAttributeMaxDynamicSharedMemorySize, SMEMB);
    cudaFuncSetAttribute(mma_gemm<EPI_AV>,    cudaFuncAttributeMaxDynamicSharedMemorySize, SMEMB);
    cudaFuncSetAttribute(mma_gemm<EPI_GELU>,  cudaFuncAttributeMaxDynamicSharedMemorySize, SMEMB);
    cudaFuncSetAttribute(mma_gemm<EPI_RES>,   cudaFuncAttributeMaxDynamicSharedMemorySize, SMEMB);

    int n;
    n = LL * 3 * DD * DD; f2bf<<<(n / 4 + 255) / 256, 256>>>(qkvw, wq, n);
    n = LL * DD * DD;     f2bf<<<(n / 4 + 255) / 256, 256>>>(projw, wp, n);
    n = LL * HH * DD;     f2bf<<<(n / 4 + 255) / 256, 256>>>(fc1w, w1, n);
    n = LL * DD * HH;     f2bf<<<(n / 4 + 255) / 256, 256>>>(fc2w, w2, n);

    const float scale = 1.0f / sqrtf((float)DD);
    const long xS = (long)NPTS * DD, mS = (long)KPAD * DD;
    const long vtS = (long)DD * KPAD, aS = (long)NPTS * KPAD;
    const int Mflat = BB * NPTS;                 // 18464
    const dim3 gFlatD(3, 145, 1), gFlatH(12, 145, 1);

    for (int r = 0; r < 4; r++) {
        int curM = NPTS + r;
        build_x_mem<<<dim3(NPTS, BB), DD>>>(x_in, gx, bmem, r);
        for (int l = 0; l < LL; l++) {
            const __nv_bfloat16* Wq = wq + (long)l * 3 * DD * DD;
            const __nv_bfloat16* Wkv = Wq + (long)DD * DD;      // rows D..3D contiguous
            const float* bqp = qkvb + (long)l * 3 * DD;
            const float* bkvp = bqp + DD;                       // k bias then v bias

            // xn = LN(x, norm1) -> bf16
            ln_bf16<<<2308, 256>>>(gx, n1w + l * DD, n1b + l * DD, bxn, Mflat, 0, 0, 1.f);
            // q = xn @ Wq^T + bq -> fp32 ; q-LN (scale folded) -> bf16
            mma_gemm<EPI_QK><<<gFlatD, 256, SMEMB>>>(bxn, Wq, bqp, nullptr, gq, nullptr,
                Mflat, DD, DD, DD, DD, 0, 0, 0, 0, 0);
            ln_bf16<<<2308, 256>>>(gq, qnw + l * DD, qnb + l * DD, bq, Mflat, 0, 0, scale);
            // fused K+V: [k | v] = mem @ [Wk;Wv]^T + [bk;bv]
            dim3 gKV(6, 5, BB);
            mma_gemm<EPI_KV><<<gKV, 256, SMEMB>>>(bmem, Wkv, bkvp, nullptr, gk, bvt,
                curM, DD, DD, DD, DD, KPAD, mS, 0, mS, vtS);
            ln_bf16<<<dim3((curM + 7) / 8, BB), 256>>>(gk, knw + l * DD, knb + l * DD, bk,
                curM, mS, mS, 1.f);
            // logits = q_scaled @ k^T -> bf16
            dim3 gLog(5, 5, BB);
            mma_gemm<EPI_LOGIT><<<gLog, 256, SMEMB>>>(bq, bk, nullptr, nullptr, battn, nullptr,
                NPTS, DD, DD, DD, KPAD, 0, xS, mS, aS, 0);
            softmax_bf16<<<dim3(NPTS, BB), 256>>>(battn, curM);
            // prod = attn @ vT^T -> fp32
            dim3 gProd(3, 5, BB);
            mma_gemm<EPI_AV><<<gProd, 256, SMEMB>>>(battn, bvt, nullptr, nullptr, gtmp, nullptr,
                NPTS, KPAD, KPAD, KPAD, DD, 0, aS, vtS, xS, 0);
            // an-LN -> bf16
            ln_bf16<<<dim3((NPTS + 7) / 8, BB), 256>>>(gtmp, anw + l * DD, anb + l * DD, btmp,
                NPTS, xS, xS, 1.f);
            // x += (prodn @ proj^T + pb) * ls1
            mma_gemm<EPI_RES><<<gFlatD, 256, SMEMB>>>(btmp, wp + (long)l * DD * DD,
                projb + l * DD, ls1 + l * DD, gx, nullptr,
                Mflat, DD, DD, DD, DD, 0, 0, 0, 0, 0);
            // norm2 -> bf16
            ln_bf16<<<2308, 256>>>(gx, n2w + l * DD, n2b + l * DD, bxn, Mflat, 0, 0, 1.f);
            // h = gelu(xn @ fc1^T + b1) -> bf16
            mma_gemm<EPI_GELU><<<gFlatH, 256, SMEMB>>>(bxn, w1 + (long)l * HH * DD,
                fc1b + (long)l * HH, nullptr, bh, nullptr,
                Mflat, DD, DD, DD, HH, 0, 0, 0, 0, 0);
            // x += (h @ fc2^T + b2) * ls2
            mma_gemm<EPI_RES><<<gFlatD, 256, SMEMB>>>(bh, w2 + (long)l * DD * HH,
                fc2b + l * DD, ls2 + l * DD, gx, nullptr,
                Mflat, HH, HH, HH, DD, 0, 0, 0, 0, 0);
        }
    }
    cudaMemcpyAsync(d_out, gx, (size_t)BB * NPTS * DD * sizeof(float),
                    cudaMemcpyDeviceToDevice);
}